// round 13
// baseline (speedup 1.0000x reference)
#include <cuda_runtime.h>
#include <cuda_bf16.h>

// ---------------------------------------------------------------------------
// 18-qubit statevector fidelity |<psi2|psi1>|^2, hardware-efficient ansatz.
// R13: ONE persistent kernel. 512 co-resident blocks, software grid barriers
// (two-phase sense-reversal, threadfence-ordered) replace 8 kernel launches.
// Inside: prep (block 0) | A:G0lo | B:G0hi,CZ0,G1hi | A:G1lo,CZ1,G2lo |
// B:G2hi,CZ2,G3hi | A:G3lo,CZ3,G4lo | B:G4hi,CZ4,G5hi | A:G5lo,CZ5 | reduce.
// Phase bodies = R12's verified 2-transpose windows (R7 swizzle, fmaf chains).
// ---------------------------------------------------------------------------

#define NQ 18
#define NL 6
#define NSTATE (1 << NQ)
#define NBLK 512

__device__ float2 d_psi[2][NSTATE];
__device__ float4 d_mats[2][NL][NQ][2];
__device__ double d_acc[2];
__device__ unsigned d_bar_arrive;   // static-zero; self-restoring
__device__ unsigned d_bar_gen;

__device__ __forceinline__ float2 cmulh(float2 a, float2 b) {
    return make_float2(a.x * b.x - a.y * b.y, a.x * b.y + a.y * b.x);
}
__device__ __forceinline__ float2 caddh(float2 a, float2 b) {
    return make_float2(a.x + b.x, a.y + b.y);
}
__device__ __forceinline__ float2 rscaleh(float r, float2 v) {
    return make_float2(r * v.x, r * v.y);
}

// ---- software grid barrier (all NBLK blocks co-resident) -------------------
__device__ __forceinline__ void grid_barrier() {
    __syncthreads();
    if (threadIdx.x == 0) {
        volatile unsigned* genp = &d_bar_gen;
        unsigned gen = *genp;
        __threadfence();
        unsigned ticket = atomicAdd(&d_bar_arrive, 1u);
        if (ticket == NBLK - 1) {
            d_bar_arrive = 0u;
            __threadfence();
            atomicAdd(&d_bar_gen, 1u);
        } else {
            while (*genp == gen) { __nanosleep(64); }
        }
        __threadfence();
    }
    __syncthreads();
}

__device__ __forceinline__ void compute_mat(int s, int l, int q,
                                            const float* __restrict__ x1,
                                            const float* __restrict__ x2,
                                            const float* __restrict__ iscale,
                                            const float* __restrict__ var,
                                            float4& o0, float4& o1) {
    const float* x = s ? x2 : x1;
    float a = iscale[l * NQ + q] * x[q];
    float b = var[l * 2 * NQ + q];
    float c = var[l * 2 * NQ + NQ + q];

    float sa, ca, sb, cb, sc, cc;
    sincosf(0.5f * a, &sa, &ca);
    sincosf(0.5f * b, &sb, &cb);
    sincosf(0.5f * c, &sc, &cc);

    float2 X00 = make_float2(ca, 0.f), X01 = make_float2(0.f, -sa);
    float2 X10 = make_float2(0.f, -sa), X11 = make_float2(ca, 0.f);
    float2 M100 = caddh(rscaleh(cb, X00), rscaleh(-sb, X10));
    float2 M101 = caddh(rscaleh(cb, X01), rscaleh(-sb, X11));
    float2 M110 = caddh(rscaleh(sb, X00), rscaleh(cb, X10));
    float2 M111 = caddh(rscaleh(sb, X01), rscaleh(cb, X11));
    float2 e0 = make_float2(cc, -sc);
    float2 e1 = make_float2(cc, sc);
    float2 m00 = cmulh(e0, M100);
    float2 m01 = cmulh(e0, M101);
    float2 m10 = cmulh(e1, M110);
    float2 m11 = cmulh(e1, M111);
    o0 = make_float4(m00.x, m00.y, m01.x, m01.y);
    o1 = make_float4(m10.x, m10.y, m11.x, m11.y);
}

__device__ __forceinline__ void gate_pair(float2& a, float2& b, float4 c0, float4 c1) {
    float nax = fmaf(c0.z, b.x, fmaf(-c0.w, b.y, fmaf(c0.x, a.x, -c0.y * a.y)));
    float nay = fmaf(c0.z, b.y, fmaf(c0.w, b.x, fmaf(c0.x, a.y, c0.y * a.x)));
    float nbx = fmaf(c1.z, b.x, fmaf(-c1.w, b.y, fmaf(c1.x, a.x, -c1.y * a.y)));
    float nby = fmaf(c1.z, b.y, fmaf(c1.w, b.x, fmaf(c1.x, a.y, c1.y * a.x)));
    a = make_float2(nax, nay);
    b = make_float2(nbx, nby);
}

__device__ __forceinline__ float2 gate_shfl(float2 v, int mask,
                                            float cax, float cay, float cbx, float cby) {
    float px = __shfl_xor_sync(0xFFFFFFFFu, v.x, mask);
    float py = __shfl_xor_sync(0xFFFFFFFFu, v.y, mask);
    float rx = fmaf(cbx, px, fmaf(-cby, py, fmaf(cax, v.x, -cay * v.y)));
    float ry = fmaf(cbx, py, fmaf(cby, px, fmaf(cax, v.y, cay * v.x)));
    return make_float2(rx, ry);
}

__device__ __forceinline__ unsigned swz(unsigned l) {
    return l ^ ((l >> 4) & 3u);
}

#define SHFL_GATE_M(M, j, mask)                                               \
    {                                                                         \
        float4 c0 = (M)[2 * (j)], c1 = (M)[2 * (j) + 1];                      \
        bool hi = (lane & (mask)) != 0;                                       \
        float cax = hi ? c1.z : c0.x;                                         \
        float cay = hi ? c1.w : c0.y;                                         \
        float cbx = hi ? c1.x : c0.z;                                         \
        float cby = hi ? c1.y : c0.w;                                         \
        _Pragma("unroll") for (int k = 0; k < 4; k++)                         \
            v[k] = gate_shfl(v[k], (mask), cax, cay, cbx, cby);               \
    }

// ---------------------------------------------------------------------------
// Window-A phase body: gates q0-9 of l1 (and l2 if >=0), CZ after l1 round.
// ---------------------------------------------------------------------------
__device__ __noinline__ void doA(int s, unsigned sub, int tid,
                                 int l1, int l2, int czf, int init,
                                 float2* sm, float4* sM) {
    int lane = tid & 31;
    unsigned w = (unsigned)(tid >> 5);
    unsigned blkbase = sub << 10;
    float2* psi = d_psi[s];

    if (tid < 20) sM[tid] = (&d_mats[s][l1][0][0])[tid];
    if (l2 >= 0 && tid >= 32 && tid < 52) sM[20 + tid - 32] = (&d_mats[s][l2][0][0])[tid - 32];

    unsigned l1i = ((unsigned)lane << 2) | (w << 7);
    unsigned base2 = ((unsigned)lane & 15u) | (((unsigned)lane >> 4) << 9) | (w << 4);
    float2 v[4];

    if (init) {
#pragma unroll
        for (int k = 0; k < 4; k++) v[k] = make_float2(0.f, 0.f);
        if ((blkbase | l1i) == 0) v[0] = make_float2(1.f, 0.f);
    } else {
        const float4* p4 = (const float4*)(psi + blkbase + l1i);
        float4 a = p4[0], b = p4[1];
        v[0] = make_float2(a.x, a.y);
        v[1] = make_float2(a.z, a.w);
        v[2] = make_float2(b.x, b.y);
        v[3] = make_float2(b.z, b.w);
    }
    __syncthreads();                                // sM ready

    // round 1, m1: q0 (k s1), q1 (k s2), q2-6 (lane shfl)
    {
        float4 c0 = sM[0], c1 = sM[1];
        gate_pair(v[0], v[1], c0, c1);
        gate_pair(v[2], v[3], c0, c1);
    }
    {
        float4 c0 = sM[2], c1 = sM[3];
        gate_pair(v[0], v[2], c0, c1);
        gate_pair(v[1], v[3], c0, c1);
    }
    SHFL_GATE_M(sM, 2, 1)
    SHFL_GATE_M(sM, 3, 2)
    SHFL_GATE_M(sM, 4, 4)
    SHFL_GATE_M(sM, 5, 8)
    SHFL_GATE_M(sM, 6, 16)

    // T1: m1 -> m2
    unsigned sb1 = swz(l1i);
#pragma unroll
    for (int k = 0; k < 4; k++) sm[sb1 ^ (unsigned)k] = v[k];
    __syncthreads();
    unsigned sb2 = swz(base2);
#pragma unroll
    for (int k = 0; k < 4; k++) v[k] = sm[sb2 + ((unsigned)k << 7)];

    // round 1, m2: q7, q8, q9
    {
        float4 c0 = sM[14], c1 = sM[15];
        gate_pair(v[0], v[1], c0, c1);
        gate_pair(v[2], v[3], c0, c1);
    }
    {
        float4 c0 = sM[16], c1 = sM[17];
        gate_pair(v[0], v[2], c0, c1);
        gate_pair(v[1], v[3], c0, c1);
    }
    SHFL_GATE_M(sM, 9, 16)

    if (czf >= 0) {
#pragma unroll
        for (int k = 0; k < 4; k++) {
            unsigned g = blkbase + base2 + ((unsigned)k << 7);
            unsigned tm = g & (g >> 1) & 0x1FFFFu;
            if (__popc(tm) & 1) {
                v[k].x = -v[k].x;
                v[k].y = -v[k].y;
            }
        }
    }

    if (l2 < 0) {
#pragma unroll
        for (int k = 0; k < 4; k++)
            psi[blkbase + base2 + ((unsigned)k << 7)] = v[k];
        return;
    }

    const float4* M2 = sM + 20;
    // round 2, m2 first (same-layer gates commute): q7, q8, q9
    {
        float4 c0 = M2[14], c1 = M2[15];
        gate_pair(v[0], v[1], c0, c1);
        gate_pair(v[2], v[3], c0, c1);
    }
    {
        float4 c0 = M2[16], c1 = M2[17];
        gate_pair(v[0], v[2], c0, c1);
        gate_pair(v[1], v[3], c0, c1);
    }
    SHFL_GATE_M(M2, 9, 16)

    // T-back: m2 -> m1
    __syncthreads();
#pragma unroll
    for (int k = 0; k < 4; k++) sm[sb2 + ((unsigned)k << 7)] = v[k];
    __syncthreads();
#pragma unroll
    for (int k = 0; k < 4; k++) v[k] = sm[sb1 ^ (unsigned)k];

    // round 2, m1: q0, q1, q2-6
    {
        float4 c0 = M2[0], c1 = M2[1];
        gate_pair(v[0], v[1], c0, c1);
        gate_pair(v[2], v[3], c0, c1);
    }
    {
        float4 c0 = M2[2], c1 = M2[3];
        gate_pair(v[0], v[2], c0, c1);
        gate_pair(v[1], v[3], c0, c1);
    }
    SHFL_GATE_M(M2, 2, 1)
    SHFL_GATE_M(M2, 3, 2)
    SHFL_GATE_M(M2, 4, 4)
    SHFL_GATE_M(M2, 5, 8)
    SHFL_GATE_M(M2, 6, 16)

    {
        float4* p4 = (float4*)(psi + blkbase + l1i);
        p4[0] = make_float4(v[0].x, v[0].y, v[1].x, v[1].y);
        p4[1] = make_float4(v[2].x, v[2].y, v[3].x, v[3].y);
    }
}

// ---------------------------------------------------------------------------
// Window-B phase body: gates q10-17 of l1 (and l2 if >=0), CZ after l1 round.
// Window {0,1,10..17}: g(l) = (l&3) | rest<<2 | (l>>2)<<10.
// ---------------------------------------------------------------------------
__device__ __noinline__ void doB(int s, unsigned rest, int tid,
                                 int l1, int l2, int czf,
                                 float2* sm, float4* sM) {
    int lane = tid & 31;
    unsigned w = (unsigned)(tid >> 5);
    float2* psi = d_psi[s];

    if (tid < 16) sM[tid] = (&d_mats[s][l1][10][0])[tid];
    if (l2 >= 0 && tid >= 32 && tid < 48) sM[16 + tid - 32] = (&d_mats[s][l2][10][0])[tid - 32];

    unsigned l1i = ((unsigned)lane << 2) | (w << 7);
    unsigned g1 = (l1i & 3u) | (rest << 2) | ((l1i >> 2) << 10);
    unsigned base2 = ((unsigned)lane & 15u) | (((unsigned)lane >> 4) << 9) | (w << 4);

    float2 v[4];
    {
        const float4* p4 = (const float4*)(psi + g1);
        float4 a = p4[0], b = p4[1];
        v[0] = make_float2(a.x, a.y);
        v[1] = make_float2(a.z, a.w);
        v[2] = make_float2(b.x, b.y);
        v[3] = make_float2(b.z, b.w);
    }
    __syncthreads();                                // sM ready

    // round 1, m1: q10..q14 (lane shfl)
    SHFL_GATE_M(sM, 0, 1)
    SHFL_GATE_M(sM, 1, 2)
    SHFL_GATE_M(sM, 2, 4)
    SHFL_GATE_M(sM, 3, 8)
    SHFL_GATE_M(sM, 4, 16)

    unsigned sb1 = swz(l1i);
#pragma unroll
    for (int k = 0; k < 4; k++) sm[sb1 ^ (unsigned)k] = v[k];
    __syncthreads();
    unsigned sb2 = swz(base2);
#pragma unroll
    for (int k = 0; k < 4; k++) v[k] = sm[sb2 + ((unsigned)k << 7)];

    // round 1, m2: q15, q16, q17
    {
        float4 c0 = sM[10], c1 = sM[11];
        gate_pair(v[0], v[1], c0, c1);
        gate_pair(v[2], v[3], c0, c1);
    }
    {
        float4 c0 = sM[12], c1 = sM[13];
        gate_pair(v[0], v[2], c0, c1);
        gate_pair(v[1], v[3], c0, c1);
    }
    SHFL_GATE_M(sM, 7, 16)

    if (czf >= 0) {
#pragma unroll
        for (int k = 0; k < 4; k++) {
            unsigned l2i = base2 | ((unsigned)k << 7);
            unsigned g = (l2i & 3u) | (rest << 2) | ((l2i >> 2) << 10);
            unsigned tm = g & (g >> 1) & 0x1FFFFu;
            if (__popc(tm) & 1) {
                v[k].x = -v[k].x;
                v[k].y = -v[k].y;
            }
        }
    }

    if (l2 < 0) {
#pragma unroll
        for (int k = 0; k < 4; k++) {
            unsigned l2i = base2 | ((unsigned)k << 7);
            unsigned g = (l2i & 3u) | (rest << 2) | ((l2i >> 2) << 10);
            psi[g] = v[k];
        }
        return;
    }

    const float4* M2 = sM + 16;
    // round 2, m2 first: q15, q16, q17
    {
        float4 c0 = M2[10], c1 = M2[11];
        gate_pair(v[0], v[1], c0, c1);
        gate_pair(v[2], v[3], c0, c1);
    }
    {
        float4 c0 = M2[12], c1 = M2[13];
        gate_pair(v[0], v[2], c0, c1);
        gate_pair(v[1], v[3], c0, c1);
    }
    SHFL_GATE_M(M2, 7, 16)

    // T-back
    __syncthreads();
#pragma unroll
    for (int k = 0; k < 4; k++) sm[sb2 + ((unsigned)k << 7)] = v[k];
    __syncthreads();
#pragma unroll
    for (int k = 0; k < 4; k++) v[k] = sm[sb1 ^ (unsigned)k];

    // round 2, m1: q10..q14
    SHFL_GATE_M(M2, 0, 1)
    SHFL_GATE_M(M2, 1, 2)
    SHFL_GATE_M(M2, 2, 4)
    SHFL_GATE_M(M2, 3, 8)
    SHFL_GATE_M(M2, 4, 16)

    {
        float4* p4 = (float4*)(psi + g1);
        p4[0] = make_float4(v[0].x, v[0].y, v[1].x, v[1].y);
        p4[1] = make_float4(v[2].x, v[2].y, v[3].x, v[3].y);
    }
}

// ---------------------------------------------------------------------------
// The single persistent kernel.
// ---------------------------------------------------------------------------
__global__ void __launch_bounds__(256, 4) qk_all(const float* __restrict__ x1,
                                                 const float* __restrict__ x2,
                                                 const float* __restrict__ iscale,
                                                 const float* __restrict__ var,
                                                 float* __restrict__ out) {
    __shared__ float2 sm[1024];
    __shared__ float4 sM[40];
    int tid = threadIdx.x;
    int blk = blockIdx.x;
    int s = blk >> 8;
    unsigned sub = (unsigned)(blk & 255);

    // prep: block 0 computes all 216 fused matrices + resets accumulators
    if (blk == 0) {
        if (tid == 0) {
            d_acc[0] = 0.0;
            d_acc[1] = 0.0;
        }
        if (tid < 2 * NL * NQ) {
            int ss = tid / (NL * NQ);
            int r = tid % (NL * NQ);
            int l = r / NQ;
            int q = r % NQ;
            float4 o0, o1;
            compute_mat(ss, l, q, x1, x2, iscale, var, o0, o1);
            d_mats[ss][l][q][0] = o0;
            d_mats[ss][l][q][1] = o1;
        }
    }
    grid_barrier();

    doA(s, sub, tid, 0, -1, -1, 1, sm, sM);   grid_barrier();
    doB(s, sub, tid, 0, 1, 0, sm, sM);        grid_barrier();
    doA(s, sub, tid, 1, 2, 1, 0, sm, sM);     grid_barrier();
    doB(s, sub, tid, 2, 3, 2, sm, sM);        grid_barrier();
    doA(s, sub, tid, 3, 4, 3, 0, sm, sM);     grid_barrier();
    doB(s, sub, tid, 4, 5, 4, sm, sM);        grid_barrier();
    doA(s, sub, tid, 5, -1, 5, 0, sm, sM);    grid_barrier();

    // overlap reduction: 131072 threads x 2 amps
    {
        int gt = blk * 256 + tid;
        double re = 0.0, im = 0.0;
        for (int i = gt; i < NSTATE; i += NBLK * 256) {
            float2 a = d_psi[0][i];
            float2 b = d_psi[1][i];
            re += (double)b.x * a.x + (double)b.y * a.y;
            im += (double)b.x * a.y - (double)b.y * a.x;
        }
#pragma unroll
        for (int o = 16; o > 0; o >>= 1) {
            re += __shfl_down_sync(0xFFFFFFFFu, re, o);
            im += __shfl_down_sync(0xFFFFFFFFu, im, o);
        }
        if ((tid & 31) == 0) {
            atomicAdd(&d_acc[0], re);
            atomicAdd(&d_acc[1], im);
        }
    }
    grid_barrier();

    if (blk == 0 && tid == 0) {
        double rr = d_acc[0], ii = d_acc[1];
        out[0] = (float)(rr * rr + ii * ii);
    }
}

extern "C" void kernel_launch(void* const* d_in, const int* in_sizes, int n_in,
                              void* d_out, int out_size) {
    const float* x1 = (const float*)d_in[0];
    const float* x2 = (const float*)d_in[1];
    const float* iscale = (const float*)d_in[2];
    const float* var = (const float*)d_in[3];

    qk_all<<<NBLK, 256>>>(x1, x2, iscale, var, (float*)d_out);
}

// round 14
// speedup vs baseline: 1.2541x; 1.2541x over previous
#include <cuda_runtime.h>
#include <cuda_bf16.h>

// ---------------------------------------------------------------------------
// 18-qubit statevector fidelity |<psi2|psi1>|^2, hardware-efficient ansatz.
// R14 = R11 staircase (7 pass kernels, separate one-time prep kernel) +
//   (a) fused kernels use 2 smem transposes (round 2 applies m2 gates first,
//       transposes back, applies m1 gates, stores coalesced m1 layout)
//   (b) reduce + |ov|^2 fused via fence+counter last-block pattern.
// Schedule: prep | A:G0lo(init) | B:G0hi,CZ0,G1hi | A:G1lo,CZ1,G2lo |
//           B:G2hi,CZ2,G3hi | A:G3lo,CZ3,G4lo | B:G4hi,CZ4,G5hi |
//           A:G5lo,CZ5 | reduce(+final)
// ---------------------------------------------------------------------------

#define NQ 18
#define NL 6
#define NSTATE (1 << NQ)

__device__ float2 d_psi[2][NSTATE];
// per (s,l,q): f4[0]=(m00.x,m00.y,m01.x,m01.y), f4[1]=(m10.x,m10.y,m11.x,m11.y)
__device__ float4 d_mats[2][NL][NQ][2];
__device__ double d_acc[2];
__device__ unsigned d_count;

__device__ __forceinline__ float2 cmulh(float2 a, float2 b) {
    return make_float2(a.x * b.x - a.y * b.y, a.x * b.y + a.y * b.x);
}
__device__ __forceinline__ float2 caddh(float2 a, float2 b) {
    return make_float2(a.x + b.x, a.y + b.y);
}
__device__ __forceinline__ float2 rscaleh(float r, float2 v) {
    return make_float2(r * v.x, r * v.y);
}

__global__ void qk_prep(const float* __restrict__ x1, const float* __restrict__ x2,
                        const float* __restrict__ iscale, const float* __restrict__ var) {
    int t = threadIdx.x;
    if (t == 0) {
        d_acc[0] = 0.0;
        d_acc[1] = 0.0;
        d_count = 0u;
    }
    if (t >= 2 * NL * NQ) return;
    int s = t / (NL * NQ);
    int r = t % (NL * NQ);
    int l = r / NQ;
    int q = r % NQ;
    const float* x = s ? x2 : x1;

    float a = iscale[l * NQ + q] * x[q];
    float b = var[l * 2 * NQ + q];
    float c = var[l * 2 * NQ + NQ + q];

    float sa, ca, sb, cb, sc, cc;
    sincosf(0.5f * a, &sa, &ca);
    sincosf(0.5f * b, &sb, &cb);
    sincosf(0.5f * c, &sc, &cc);

    float2 X00 = make_float2(ca, 0.f), X01 = make_float2(0.f, -sa);
    float2 X10 = make_float2(0.f, -sa), X11 = make_float2(ca, 0.f);
    float2 M100 = caddh(rscaleh(cb, X00), rscaleh(-sb, X10));
    float2 M101 = caddh(rscaleh(cb, X01), rscaleh(-sb, X11));
    float2 M110 = caddh(rscaleh(sb, X00), rscaleh(cb, X10));
    float2 M111 = caddh(rscaleh(sb, X01), rscaleh(cb, X11));
    float2 e0 = make_float2(cc, -sc);
    float2 e1 = make_float2(cc, sc);
    float2 m00 = cmulh(e0, M100);
    float2 m01 = cmulh(e0, M101);
    float2 m10 = cmulh(e1, M110);
    float2 m11 = cmulh(e1, M111);

    d_mats[s][l][q][0] = make_float4(m00.x, m00.y, m01.x, m01.y);
    d_mats[s][l][q][1] = make_float4(m10.x, m10.y, m11.x, m11.y);
}

__device__ __forceinline__ void gate_pair(float2& a, float2& b, float4 c0, float4 c1) {
    float nax = fmaf(c0.z, b.x, fmaf(-c0.w, b.y, fmaf(c0.x, a.x, -c0.y * a.y)));
    float nay = fmaf(c0.z, b.y, fmaf(c0.w, b.x, fmaf(c0.x, a.y, c0.y * a.x)));
    float nbx = fmaf(c1.z, b.x, fmaf(-c1.w, b.y, fmaf(c1.x, a.x, -c1.y * a.y)));
    float nby = fmaf(c1.z, b.y, fmaf(c1.w, b.x, fmaf(c1.x, a.y, c1.y * a.x)));
    a = make_float2(nax, nay);
    b = make_float2(nbx, nby);
}

__device__ __forceinline__ float2 gate_shfl(float2 v, int mask,
                                            float cax, float cay, float cbx, float cby) {
    float px = __shfl_xor_sync(0xFFFFFFFFu, v.x, mask);
    float py = __shfl_xor_sync(0xFFFFFFFFu, v.y, mask);
    float rx = fmaf(cbx, px, fmaf(-cby, py, fmaf(cax, v.x, -cay * v.y)));
    float ry = fmaf(cbx, py, fmaf(cby, px, fmaf(cax, v.y, cay * v.x)));
    return make_float2(rx, ry);
}

// smem swizzle (R7/R11, conflict-free both transpose directions)
__device__ __forceinline__ unsigned swz(unsigned l) {
    return l ^ ((l >> 4) & 3u);
}

#define SHFL_GATE_M(M, j, mask)                                               \
    {                                                                         \
        float4 c0 = (M)[2 * (j)], c1 = (M)[2 * (j) + 1];                      \
        bool hi = (lane & (mask)) != 0;                                       \
        float cax = hi ? c1.z : c0.x;                                         \
        float cay = hi ? c1.w : c0.y;                                         \
        float cbx = hi ? c1.x : c0.z;                                         \
        float cby = hi ? c1.y : c0.w;                                         \
        _Pragma("unroll") for (int k = 0; k < 4; k++)                         \
            v[k] = gate_shfl(v[k], (mask), cax, cay, cbx, cby);               \
    }

// ---------------------------------------------------------------------------
// Window-A kernel: gates q0-9 of l1 (and l2 if >=0), CZ after l1 round.
// m1: l = k | lane<<2 | w<<7 ; m2: l = (lane&15) | ((lane>>4)<<9) | w<<4 | k<<7
// Fused: m1(l1), T1, m2(l1), CZ, m2(l2), T-back, m1(l2), store m1 (coalesced).
// ---------------------------------------------------------------------------
__global__ void __launch_bounds__(256) qk_A(int l1, int l2, int czf, int init) {
    __shared__ float2 sm[1024];
    __shared__ float4 sM[40];
    int tid = threadIdx.x;
    int lane = tid & 31;
    unsigned w = (unsigned)(tid >> 5);
    int blk = blockIdx.x;
    int s = blk >> 8;
    unsigned blkbase = ((unsigned)(blk & 255)) << 10;
    float2* psi = d_psi[s];

    if (tid < 20) sM[tid] = (&d_mats[s][l1][0][0])[tid];
    if (l2 >= 0 && tid >= 32 && tid < 52) sM[20 + tid - 32] = (&d_mats[s][l2][0][0])[tid - 32];

    unsigned l1i = ((unsigned)lane << 2) | (w << 7);
    unsigned base2 = ((unsigned)lane & 15u) | (((unsigned)lane >> 4) << 9) | (w << 4);
    float2 v[4];

    if (init) {
#pragma unroll
        for (int k = 0; k < 4; k++) v[k] = make_float2(0.f, 0.f);
        if ((blkbase | l1i) == 0) v[0] = make_float2(1.f, 0.f);
    } else {
        const float4* p4 = (const float4*)(psi + blkbase + l1i);
        float4 a = p4[0], b = p4[1];
        v[0] = make_float2(a.x, a.y);
        v[1] = make_float2(a.z, a.w);
        v[2] = make_float2(b.x, b.y);
        v[3] = make_float2(b.z, b.w);
    }
    __syncthreads();                                // sM ready

    // round 1, m1: q0 (k s1), q1 (k s2), q2-6 (lane shfl)
    {
        float4 c0 = sM[0], c1 = sM[1];
        gate_pair(v[0], v[1], c0, c1);
        gate_pair(v[2], v[3], c0, c1);
    }
    {
        float4 c0 = sM[2], c1 = sM[3];
        gate_pair(v[0], v[2], c0, c1);
        gate_pair(v[1], v[3], c0, c1);
    }
    SHFL_GATE_M(sM, 2, 1)
    SHFL_GATE_M(sM, 3, 2)
    SHFL_GATE_M(sM, 4, 4)
    SHFL_GATE_M(sM, 5, 8)
    SHFL_GATE_M(sM, 6, 16)

    // T1: m1 -> m2
    unsigned sb1 = swz(l1i);
#pragma unroll
    for (int k = 0; k < 4; k++) sm[sb1 ^ (unsigned)k] = v[k];
    __syncthreads();
    unsigned sb2 = swz(base2);
#pragma unroll
    for (int k = 0; k < 4; k++) v[k] = sm[sb2 + ((unsigned)k << 7)];

    // round 1, m2: q7 (k' s1), q8 (k' s2), q9 (lane bit4 shfl)
    {
        float4 c0 = sM[14], c1 = sM[15];
        gate_pair(v[0], v[1], c0, c1);
        gate_pair(v[2], v[3], c0, c1);
    }
    {
        float4 c0 = sM[16], c1 = sM[17];
        gate_pair(v[0], v[2], c0, c1);
        gate_pair(v[1], v[3], c0, c1);
    }
    SHFL_GATE_M(sM, 9, 16)

    // CZ chain sign after l1 round
    if (czf >= 0) {
#pragma unroll
        for (int k = 0; k < 4; k++) {
            unsigned g = blkbase + base2 + ((unsigned)k << 7);
            unsigned tm = g & (g >> 1) & 0x1FFFFu;
            if (__popc(tm) & 1) {
                v[k].x = -v[k].x;
                v[k].y = -v[k].y;
            }
        }
    }

    if (l2 < 0) {
#pragma unroll
        for (int k = 0; k < 4; k++)
            psi[blkbase + base2 + ((unsigned)k << 7)] = v[k];
        return;
    }

    const float4* M2 = sM + 20;
    // round 2, m2 gates first (same-layer gates commute): q7, q8, q9
    {
        float4 c0 = M2[14], c1 = M2[15];
        gate_pair(v[0], v[1], c0, c1);
        gate_pair(v[2], v[3], c0, c1);
    }
    {
        float4 c0 = M2[16], c1 = M2[17];
        gate_pair(v[0], v[2], c0, c1);
        gate_pair(v[1], v[3], c0, c1);
    }
    SHFL_GATE_M(M2, 9, 16)

    // T-back: m2 -> m1
    __syncthreads();
#pragma unroll
    for (int k = 0; k < 4; k++) sm[sb2 + ((unsigned)k << 7)] = v[k];
    __syncthreads();
#pragma unroll
    for (int k = 0; k < 4; k++) v[k] = sm[sb1 ^ (unsigned)k];

    // round 2, m1: q0, q1, q2-6
    {
        float4 c0 = M2[0], c1 = M2[1];
        gate_pair(v[0], v[1], c0, c1);
        gate_pair(v[2], v[3], c0, c1);
    }
    {
        float4 c0 = M2[2], c1 = M2[3];
        gate_pair(v[0], v[2], c0, c1);
        gate_pair(v[1], v[3], c0, c1);
    }
    SHFL_GATE_M(M2, 2, 1)
    SHFL_GATE_M(M2, 3, 2)
    SHFL_GATE_M(M2, 4, 4)
    SHFL_GATE_M(M2, 5, 8)
    SHFL_GATE_M(M2, 6, 16)

    // store m1 (fully coalesced float4s)
    {
        float4* p4 = (float4*)(psi + blkbase + l1i);
        p4[0] = make_float4(v[0].x, v[0].y, v[1].x, v[1].y);
        p4[1] = make_float4(v[2].x, v[2].y, v[3].x, v[3].y);
    }
}

// ---------------------------------------------------------------------------
// Window-B kernel: gates q10-17 of l1 (and l2 if >=0), CZ after l1 round.
// Window {0,1,10..17}: g(l) = (l&3) | rest<<2 | (l>>2)<<10.
// ---------------------------------------------------------------------------
__global__ void __launch_bounds__(256) qk_B(int l1, int l2, int czf) {
    __shared__ float2 sm[1024];
    __shared__ float4 sM[32];
    int tid = threadIdx.x;
    int lane = tid & 31;
    unsigned w = (unsigned)(tid >> 5);
    int blk = blockIdx.x;
    int s = blk >> 8;
    unsigned rest = (unsigned)(blk & 255);
    float2* psi = d_psi[s];

    if (tid < 16) sM[tid] = (&d_mats[s][l1][10][0])[tid];
    if (l2 >= 0 && tid >= 32 && tid < 48) sM[16 + tid - 32] = (&d_mats[s][l2][10][0])[tid - 32];

    unsigned l1i = ((unsigned)lane << 2) | (w << 7);
    unsigned g1 = (l1i & 3u) | (rest << 2) | ((l1i >> 2) << 10);
    unsigned base2 = ((unsigned)lane & 15u) | (((unsigned)lane >> 4) << 9) | (w << 4);

    float2 v[4];
    {
        const float4* p4 = (const float4*)(psi + g1);
        float4 a = p4[0], b = p4[1];
        v[0] = make_float2(a.x, a.y);
        v[1] = make_float2(a.z, a.w);
        v[2] = make_float2(b.x, b.y);
        v[3] = make_float2(b.z, b.w);
    }
    __syncthreads();                                // sM ready

    // round 1, m1: q10..q14 (lane shfl)
    SHFL_GATE_M(sM, 0, 1)
    SHFL_GATE_M(sM, 1, 2)
    SHFL_GATE_M(sM, 2, 4)
    SHFL_GATE_M(sM, 3, 8)
    SHFL_GATE_M(sM, 4, 16)

    // T1
    unsigned sb1 = swz(l1i);
#pragma unroll
    for (int k = 0; k < 4; k++) sm[sb1 ^ (unsigned)k] = v[k];
    __syncthreads();
    unsigned sb2 = swz(base2);
#pragma unroll
    for (int k = 0; k < 4; k++) v[k] = sm[sb2 + ((unsigned)k << 7)];

    // round 1, m2: q15 (k' s1), q16 (k' s2), q17 (lane bit4 shfl)
    {
        float4 c0 = sM[10], c1 = sM[11];
        gate_pair(v[0], v[1], c0, c1);
        gate_pair(v[2], v[3], c0, c1);
    }
    {
        float4 c0 = sM[12], c1 = sM[13];
        gate_pair(v[0], v[2], c0, c1);
        gate_pair(v[1], v[3], c0, c1);
    }
    SHFL_GATE_M(sM, 7, 16)

    // CZ chain sign
    if (czf >= 0) {
#pragma unroll
        for (int k = 0; k < 4; k++) {
            unsigned l2i = base2 | ((unsigned)k << 7);
            unsigned g = (l2i & 3u) | (rest << 2) | ((l2i >> 2) << 10);
            unsigned tm = g & (g >> 1) & 0x1FFFFu;
            if (__popc(tm) & 1) {
                v[k].x = -v[k].x;
                v[k].y = -v[k].y;
            }
        }
    }

    if (l2 < 0) {
#pragma unroll
        for (int k = 0; k < 4; k++) {
            unsigned l2i = base2 | ((unsigned)k << 7);
            unsigned g = (l2i & 3u) | (rest << 2) | ((l2i >> 2) << 10);
            psi[g] = v[k];
        }
        return;
    }

    const float4* M2 = sM + 16;
    // round 2, m2 first: q15, q16, q17
    {
        float4 c0 = M2[10], c1 = M2[11];
        gate_pair(v[0], v[1], c0, c1);
        gate_pair(v[2], v[3], c0, c1);
    }
    {
        float4 c0 = M2[12], c1 = M2[13];
        gate_pair(v[0], v[2], c0, c1);
        gate_pair(v[1], v[3], c0, c1);
    }
    SHFL_GATE_M(M2, 7, 16)

    // T-back
    __syncthreads();
#pragma unroll
    for (int k = 0; k < 4; k++) sm[sb2 + ((unsigned)k << 7)] = v[k];
    __syncthreads();
#pragma unroll
    for (int k = 0; k < 4; k++) v[k] = sm[sb1 ^ (unsigned)k];

    // round 2, m1: q10..q14
    SHFL_GATE_M(M2, 0, 1)
    SHFL_GATE_M(M2, 1, 2)
    SHFL_GATE_M(M2, 2, 4)
    SHFL_GATE_M(M2, 3, 8)
    SHFL_GATE_M(M2, 4, 16)

    // store m1 (same pattern as load)
    {
        float4* p4 = (float4*)(psi + g1);
        p4[0] = make_float4(v[0].x, v[0].y, v[1].x, v[1].y);
        p4[1] = make_float4(v[2].x, v[2].y, v[3].x, v[3].y);
    }
}

// ---------------------------------------------------------------------------
// Overlap reduction + finalization (last arriving block computes |ov|^2)
// ---------------------------------------------------------------------------
__global__ void qk_reduce(float* out) {
    int t = blockIdx.x * blockDim.x + threadIdx.x;
    int nthreads = gridDim.x * blockDim.x;
    double re = 0.0, im = 0.0;
    for (int i = t; i < NSTATE; i += nthreads) {
        float2 a = d_psi[0][i];
        float2 b = d_psi[1][i];
        re += (double)b.x * a.x + (double)b.y * a.y;
        im += (double)b.x * a.y - (double)b.y * a.x;
    }
#pragma unroll
    for (int o = 16; o > 0; o >>= 1) {
        re += __shfl_down_sync(0xFFFFFFFFu, re, o);
        im += __shfl_down_sync(0xFFFFFFFFu, im, o);
    }
    if ((threadIdx.x & 31) == 0) {
        atomicAdd(&d_acc[0], re);
        atomicAdd(&d_acc[1], im);
    }
    __syncthreads();
    if (threadIdx.x == 0) {
        __threadfence();
        unsigned done = atomicAdd(&d_count, 1u);
        if (done == gridDim.x - 1) {
            double rr = d_acc[0], ii = d_acc[1];
            out[0] = (float)(rr * rr + ii * ii);
        }
    }
}

extern "C" void kernel_launch(void* const* d_in, const int* in_sizes, int n_in,
                              void* d_out, int out_size) {
    const float* x1 = (const float*)d_in[0];
    const float* x2 = (const float*)d_in[1];
    const float* iscale = (const float*)d_in[2];
    const float* var = (const float*)d_in[3];

    qk_prep<<<1, 256>>>(x1, x2, iscale, var);
    qk_A<<<512, 256>>>(0, -1, -1, 1);               // G0(0-9), init
    qk_B<<<512, 256>>>(0, 1, 0);                    // G0hi, CZ0, G1hi
    qk_A<<<512, 256>>>(1, 2, 1, 0);                 // G1lo, CZ1, G2lo
    qk_B<<<512, 256>>>(2, 3, 2);                    // G2hi, CZ2, G3hi
    qk_A<<<512, 256>>>(3, 4, 3, 0);                 // G3lo, CZ3, G4lo
    qk_B<<<512, 256>>>(4, 5, 4);                    // G4hi, CZ4, G5hi
    qk_A<<<512, 256>>>(5, -1, 5, 0);                // G5lo, CZ5
    qk_reduce<<<148, 256>>>((float*)d_out);
}

// round 15
// speedup vs baseline: 1.3437x; 1.0714x over previous
#include <cuda_runtime.h>
#include <cuda_bf16.h>

// ---------------------------------------------------------------------------
// 18-qubit statevector fidelity |<psi2|psi1>|^2, hardware-efficient ansatz.
// R15 = staircase fusion (7 pass kernels + reduce, 8 launches) with:
//  - window B redesigned to {0,1,2, 10-17} (11 bits, 256 blocks x 512 thr):
//    lane bit 0 -> amp bit 2 makes lane-pairs 64B-contiguous, halving the
//    L1tex line count (nL 32 -> 16) for all B global loads/stores.
//  - prep inlined into P1 (each block computes its own G0lo; blocks 0/256
//    write all 216 d_mats for later kernels). No separate prep launch.
//  - 2-transpose fused bodies; reduce + |ov|^2 fused (fence+counter).
// Schedule: A:G0lo(init+prep) | B:G0hi,CZ0,G1hi | A:G1lo,CZ1,G2lo |
//           B:G2hi,CZ2,G3hi | A:G3lo,CZ3,G4lo | B:G4hi,CZ4,G5hi |
//           A:G5lo,CZ5 | reduce(+final)
// ---------------------------------------------------------------------------

#define NQ 18
#define NL 6
#define NSTATE (1 << NQ)

__device__ float2 d_psi[2][NSTATE];
// per (s,l,q): f4[0]=(m00.x,m00.y,m01.x,m01.y), f4[1]=(m10.x,m10.y,m11.x,m11.y)
__device__ float4 d_mats[2][NL][NQ][2];
__device__ double d_acc[2];
__device__ unsigned d_count;

__device__ __forceinline__ float2 cmulh(float2 a, float2 b) {
    return make_float2(a.x * b.x - a.y * b.y, a.x * b.y + a.y * b.x);
}
__device__ __forceinline__ float2 caddh(float2 a, float2 b) {
    return make_float2(a.x + b.x, a.y + b.y);
}
__device__ __forceinline__ float2 rscaleh(float r, float2 v) {
    return make_float2(r * v.x, r * v.y);
}

// fused M = RZ(c)*RY(b)*RX(a) for (state s, layer l, qubit q)
__device__ __forceinline__ void compute_mat(int s, int l, int q,
                                            const float* __restrict__ x1,
                                            const float* __restrict__ x2,
                                            const float* __restrict__ iscale,
                                            const float* __restrict__ var,
                                            float4& o0, float4& o1) {
    const float* x = s ? x2 : x1;
    float a = iscale[l * NQ + q] * x[q];
    float b = var[l * 2 * NQ + q];
    float c = var[l * 2 * NQ + NQ + q];

    float sa, ca, sb, cb, sc, cc;
    sincosf(0.5f * a, &sa, &ca);
    sincosf(0.5f * b, &sb, &cb);
    sincosf(0.5f * c, &sc, &cc);

    float2 X00 = make_float2(ca, 0.f), X01 = make_float2(0.f, -sa);
    float2 X10 = make_float2(0.f, -sa), X11 = make_float2(ca, 0.f);
    float2 M100 = caddh(rscaleh(cb, X00), rscaleh(-sb, X10));
    float2 M101 = caddh(rscaleh(cb, X01), rscaleh(-sb, X11));
    float2 M110 = caddh(rscaleh(sb, X00), rscaleh(cb, X10));
    float2 M111 = caddh(rscaleh(sb, X01), rscaleh(cb, X11));
    float2 e0 = make_float2(cc, -sc);
    float2 e1 = make_float2(cc, sc);
    float2 m00 = cmulh(e0, M100);
    float2 m01 = cmulh(e0, M101);
    float2 m10 = cmulh(e1, M110);
    float2 m11 = cmulh(e1, M111);
    o0 = make_float4(m00.x, m00.y, m01.x, m01.y);
    o1 = make_float4(m10.x, m10.y, m11.x, m11.y);
}

__device__ __forceinline__ void gate_pair(float2& a, float2& b, float4 c0, float4 c1) {
    float nax = fmaf(c0.z, b.x, fmaf(-c0.w, b.y, fmaf(c0.x, a.x, -c0.y * a.y)));
    float nay = fmaf(c0.z, b.y, fmaf(c0.w, b.x, fmaf(c0.x, a.y, c0.y * a.x)));
    float nbx = fmaf(c1.z, b.x, fmaf(-c1.w, b.y, fmaf(c1.x, a.x, -c1.y * a.y)));
    float nby = fmaf(c1.z, b.y, fmaf(c1.w, b.x, fmaf(c1.x, a.y, c1.y * a.x)));
    a = make_float2(nax, nay);
    b = make_float2(nbx, nby);
}

__device__ __forceinline__ float2 gate_shfl(float2 v, int mask,
                                            float cax, float cay, float cbx, float cby) {
    float px = __shfl_xor_sync(0xFFFFFFFFu, v.x, mask);
    float py = __shfl_xor_sync(0xFFFFFFFFu, v.y, mask);
    float rx = fmaf(cbx, px, fmaf(-cby, py, fmaf(cax, v.x, -cay * v.y)));
    float ry = fmaf(cbx, py, fmaf(cby, px, fmaf(cax, v.y, cay * v.x)));
    return make_float2(rx, ry);
}

// A swizzle (10-bit window, verified R7/R11)
__device__ __forceinline__ unsigned swzA(unsigned l) {
    return l ^ ((l >> 4) & 3u);
}
// B swizzle (11-bit window): fold bits 4,5 -> 0,1 and bit 9 -> 3.
// STS lanes vary bits 2-6; LDS lanes vary bits 0,1,2,9,10 -> both mod-16
// distinct per half-warp.
__device__ __forceinline__ unsigned swzB(unsigned l) {
    return l ^ ((l >> 4) & 3u) ^ ((l >> 6) & 8u);
}

#define SHFL_GATE_M(M, j, mask)                                               \
    {                                                                         \
        float4 c0 = (M)[2 * (j)], c1 = (M)[2 * (j) + 1];                      \
        bool hi = (lane & (mask)) != 0;                                       \
        float cax = hi ? c1.z : c0.x;                                         \
        float cay = hi ? c1.w : c0.y;                                         \
        float cbx = hi ? c1.x : c0.z;                                         \
        float cby = hi ? c1.y : c0.w;                                         \
        _Pragma("unroll") for (int k = 0; k < 4; k++)                         \
            v[k] = gate_shfl(v[k], (mask), cax, cay, cbx, cby);               \
    }

// ---------------------------------------------------------------------------
// Window-A kernel: gates q0-9 of l1 (and l2 if >=0), CZ after l1 round.
// m1: l = k | lane<<2 | w<<7 ; m2: l = (lane&15) | ((lane>>4)<<9) | w<<4 | k<<7
// init: per-block inline G0lo; blocks 0/256 also write all d_mats.
// ---------------------------------------------------------------------------
__global__ void __launch_bounds__(256) qk_A(int l1, int l2, int czf, int init,
                                            const float* __restrict__ x1,
                                            const float* __restrict__ x2,
                                            const float* __restrict__ iscale,
                                            const float* __restrict__ var) {
    __shared__ float2 sm[1024];
    __shared__ float4 sM[40];
    int tid = threadIdx.x;
    int lane = tid & 31;
    unsigned w = (unsigned)(tid >> 5);
    int blk = blockIdx.x;
    int s = blk >> 8;
    unsigned blkbase = ((unsigned)(blk & 255)) << 10;
    float2* psi = d_psi[s];

    if (init) {
        if (tid < 10) {
            float4 o0, o1;
            compute_mat(s, 0, tid, x1, x2, iscale, var, o0, o1);
            sM[2 * tid] = o0;
            sM[2 * tid + 1] = o1;
        }
        if ((blk & 255) == 0 && tid >= 32 && tid < 32 + NL * NQ) {
            int r = tid - 32;
            int l = r / NQ, q = r % NQ;
            float4 o0, o1;
            compute_mat(s, l, q, x1, x2, iscale, var, o0, o1);
            d_mats[s][l][q][0] = o0;
            d_mats[s][l][q][1] = o1;
        }
        if (blk == 0 && tid == 255) {
            d_acc[0] = 0.0;
            d_acc[1] = 0.0;
            d_count = 0u;
        }
    } else {
        if (tid < 20) sM[tid] = (&d_mats[s][l1][0][0])[tid];
        if (l2 >= 0 && tid >= 32 && tid < 52) sM[20 + tid - 32] = (&d_mats[s][l2][0][0])[tid - 32];
    }

    unsigned l1i = ((unsigned)lane << 2) | (w << 7);
    unsigned base2 = ((unsigned)lane & 15u) | (((unsigned)lane >> 4) << 9) | (w << 4);
    float2 v[4];

    if (init) {
#pragma unroll
        for (int k = 0; k < 4; k++) v[k] = make_float2(0.f, 0.f);
        if ((blkbase | l1i) == 0) v[0] = make_float2(1.f, 0.f);
    } else {
        const float4* p4 = (const float4*)(psi + blkbase + l1i);
        float4 a = p4[0], b = p4[1];
        v[0] = make_float2(a.x, a.y);
        v[1] = make_float2(a.z, a.w);
        v[2] = make_float2(b.x, b.y);
        v[3] = make_float2(b.z, b.w);
    }
    __syncthreads();                                // sM ready

    // round 1, m1: q0 (k s1), q1 (k s2), q2-6 (lane shfl)
    {
        float4 c0 = sM[0], c1 = sM[1];
        gate_pair(v[0], v[1], c0, c1);
        gate_pair(v[2], v[3], c0, c1);
    }
    {
        float4 c0 = sM[2], c1 = sM[3];
        gate_pair(v[0], v[2], c0, c1);
        gate_pair(v[1], v[3], c0, c1);
    }
    SHFL_GATE_M(sM, 2, 1)
    SHFL_GATE_M(sM, 3, 2)
    SHFL_GATE_M(sM, 4, 4)
    SHFL_GATE_M(sM, 5, 8)
    SHFL_GATE_M(sM, 6, 16)

    // T1: m1 -> m2
    unsigned sb1 = swzA(l1i);
#pragma unroll
    for (int k = 0; k < 4; k++) sm[sb1 ^ (unsigned)k] = v[k];
    __syncthreads();
    unsigned sb2 = swzA(base2);
#pragma unroll
    for (int k = 0; k < 4; k++) v[k] = sm[sb2 + ((unsigned)k << 7)];

    // round 1, m2: q7 (k' s1), q8 (k' s2), q9 (lane bit4 shfl)
    {
        float4 c0 = sM[14], c1 = sM[15];
        gate_pair(v[0], v[1], c0, c1);
        gate_pair(v[2], v[3], c0, c1);
    }
    {
        float4 c0 = sM[16], c1 = sM[17];
        gate_pair(v[0], v[2], c0, c1);
        gate_pair(v[1], v[3], c0, c1);
    }
    SHFL_GATE_M(sM, 9, 16)

    if (czf >= 0) {
#pragma unroll
        for (int k = 0; k < 4; k++) {
            unsigned g = blkbase + base2 + ((unsigned)k << 7);
            unsigned tm = g & (g >> 1) & 0x1FFFFu;
            if (__popc(tm) & 1) {
                v[k].x = -v[k].x;
                v[k].y = -v[k].y;
            }
        }
    }

    if (l2 < 0) {
#pragma unroll
        for (int k = 0; k < 4; k++)
            psi[blkbase + base2 + ((unsigned)k << 7)] = v[k];
        return;
    }

    const float4* M2 = sM + 20;
    // round 2, m2 gates first (same-layer gates commute): q7, q8, q9
    {
        float4 c0 = M2[14], c1 = M2[15];
        gate_pair(v[0], v[1], c0, c1);
        gate_pair(v[2], v[3], c0, c1);
    }
    {
        float4 c0 = M2[16], c1 = M2[17];
        gate_pair(v[0], v[2], c0, c1);
        gate_pair(v[1], v[3], c0, c1);
    }
    SHFL_GATE_M(M2, 9, 16)

    // T-back: m2 -> m1
    __syncthreads();
#pragma unroll
    for (int k = 0; k < 4; k++) sm[sb2 + ((unsigned)k << 7)] = v[k];
    __syncthreads();
#pragma unroll
    for (int k = 0; k < 4; k++) v[k] = sm[sb1 ^ (unsigned)k];

    // round 2, m1: q0, q1, q2-6
    {
        float4 c0 = M2[0], c1 = M2[1];
        gate_pair(v[0], v[1], c0, c1);
        gate_pair(v[2], v[3], c0, c1);
    }
    {
        float4 c0 = M2[2], c1 = M2[3];
        gate_pair(v[0], v[2], c0, c1);
        gate_pair(v[1], v[3], c0, c1);
    }
    SHFL_GATE_M(M2, 2, 1)
    SHFL_GATE_M(M2, 3, 2)
    SHFL_GATE_M(M2, 4, 4)
    SHFL_GATE_M(M2, 5, 8)
    SHFL_GATE_M(M2, 6, 16)

    // store m1 (fully coalesced float4s)
    {
        float4* p4 = (float4*)(psi + blkbase + l1i);
        p4[0] = make_float4(v[0].x, v[0].y, v[1].x, v[1].y);
        p4[1] = make_float4(v[2].x, v[2].y, v[3].x, v[3].y);
    }
}

// ---------------------------------------------------------------------------
// Window-B kernel (always fused): gates q10-17 of l1 and l2, CZ after l1.
// Window {0,1,2, 10..17} (11 bits): g(l) = (l&7) | rest<<3 | (l>>3)<<10.
// 256 blocks x 512 threads, 4 amps/thread.
// m1: l = k | lane<<2 | w<<7  (k: bits 0,1; lane b0 -> l2 rider; lane b1-4 ->
//     l3-6 = g10-13 shfl masks 2,4,8,16; w -> l7-10 = g14-17)
// m2: l = (lane&7) | w<<3 | k'<<7 | (lane>>3)<<9
//     (k' -> g14,15 reg; lane b3,b4 -> g16,17 shfl masks 8,16)
// ---------------------------------------------------------------------------
__global__ void __launch_bounds__(512) qk_B(int l1, int l2) {
    __shared__ float2 sm[2048];
    __shared__ float4 sM[32];
    int tid = threadIdx.x;
    int lane = tid & 31;
    unsigned w = (unsigned)(tid >> 5);              // 0..15
    int blk = blockIdx.x;                           // 0..255
    int s = blk >> 7;
    unsigned rest = (unsigned)(blk & 127);          // g bits 3-9
    float2* psi = d_psi[s];

    if (tid < 16) sM[tid] = (&d_mats[s][l1][10][0])[tid];
    if (tid >= 32 && tid < 48) sM[16 + tid - 32] = (&d_mats[s][l2][10][0])[tid - 32];

    unsigned l1i = ((unsigned)lane << 2) | (w << 7);
    unsigned g1 = (l1i & 7u) | (rest << 3) | ((l1i >> 3) << 10);

    float2 v[4];
    {
        const float4* p4 = (const float4*)(psi + g1);
        float4 a = p4[0], b = p4[1];
        v[0] = make_float2(a.x, a.y);
        v[1] = make_float2(a.z, a.w);
        v[2] = make_float2(b.x, b.y);
        v[3] = make_float2(b.z, b.w);
    }
    __syncthreads();                                // sM ready

    // round 1, m1: q10..q13 (lane shfl masks 2,4,8,16; j = q-10)
    SHFL_GATE_M(sM, 0, 2)
    SHFL_GATE_M(sM, 1, 4)
    SHFL_GATE_M(sM, 2, 8)
    SHFL_GATE_M(sM, 3, 16)

    // T1: m1 -> m2
    unsigned sb1 = swzB(l1i);
#pragma unroll
    for (int k = 0; k < 4; k++) sm[sb1 ^ (unsigned)k] = v[k];
    __syncthreads();
    unsigned l2i = ((unsigned)lane & 7u) | (w << 3) | (((unsigned)lane >> 3) << 9);
    unsigned sb2 = swzB(l2i);
#pragma unroll
    for (int k = 0; k < 4; k++) v[k] = sm[sb2 + ((unsigned)k << 7)];

    // round 1, m2: q14 (k' s1), q15 (k' s2), q16 (mask 8), q17 (mask 16)
    {
        float4 c0 = sM[8], c1 = sM[9];
        gate_pair(v[0], v[1], c0, c1);
        gate_pair(v[2], v[3], c0, c1);
    }
    {
        float4 c0 = sM[10], c1 = sM[11];
        gate_pair(v[0], v[2], c0, c1);
        gate_pair(v[1], v[3], c0, c1);
    }
    SHFL_GATE_M(sM, 6, 8)
    SHFL_GATE_M(sM, 7, 16)

    // CZ chain sign (layer l1 complete)
#pragma unroll
    for (int k = 0; k < 4; k++) {
        unsigned lk = l2i | ((unsigned)k << 7);
        unsigned g = (lk & 7u) | (rest << 3) | ((lk >> 3) << 10);
        unsigned tm = g & (g >> 1) & 0x1FFFFu;
        if (__popc(tm) & 1) {
            v[k].x = -v[k].x;
            v[k].y = -v[k].y;
        }
    }

    const float4* M2 = sM + 16;
    // round 2, m2 gates first: q14, q15, q16, q17 (layer l2)
    {
        float4 c0 = M2[8], c1 = M2[9];
        gate_pair(v[0], v[1], c0, c1);
        gate_pair(v[2], v[3], c0, c1);
    }
    {
        float4 c0 = M2[10], c1 = M2[11];
        gate_pair(v[0], v[2], c0, c1);
        gate_pair(v[1], v[3], c0, c1);
    }
    SHFL_GATE_M(M2, 6, 8)
    SHFL_GATE_M(M2, 7, 16)

    // T-back: m2 -> m1
    __syncthreads();
#pragma unroll
    for (int k = 0; k < 4; k++) sm[sb2 + ((unsigned)k << 7)] = v[k];
    __syncthreads();
#pragma unroll
    for (int k = 0; k < 4; k++) v[k] = sm[sb1 ^ (unsigned)k];

    // round 2, m1: q10..q13 (layer l2)
    SHFL_GATE_M(M2, 0, 2)
    SHFL_GATE_M(M2, 1, 4)
    SHFL_GATE_M(M2, 2, 8)
    SHFL_GATE_M(M2, 3, 16)

    // store m1 (lane-pair 64B-contiguous runs)
    {
        float4* p4 = (float4*)(psi + g1);
        p4[0] = make_float4(v[0].x, v[0].y, v[1].x, v[1].y);
        p4[1] = make_float4(v[2].x, v[2].y, v[3].x, v[3].y);
    }
}

// ---------------------------------------------------------------------------
// Overlap reduction + finalization (last arriving block computes |ov|^2)
// ---------------------------------------------------------------------------
__global__ void qk_reduce(float* out) {
    int t = blockIdx.x * blockDim.x + threadIdx.x;
    int nthreads = gridDim.x * blockDim.x;
    double re = 0.0, im = 0.0;
    for (int i = t; i < NSTATE; i += nthreads) {
        float2 a = d_psi[0][i];
        float2 b = d_psi[1][i];
        re += (double)b.x * a.x + (double)b.y * a.y;
        im += (double)b.x * a.y - (double)b.y * a.x;
    }
#pragma unroll
    for (int o = 16; o > 0; o >>= 1) {
        re += __shfl_down_sync(0xFFFFFFFFu, re, o);
        im += __shfl_down_sync(0xFFFFFFFFu, im, o);
    }
    if ((threadIdx.x & 31) == 0) {
        atomicAdd(&d_acc[0], re);
        atomicAdd(&d_acc[1], im);
    }
    __syncthreads();
    if (threadIdx.x == 0) {
        __threadfence();
        unsigned done = atomicAdd(&d_count, 1u);
        if (done == gridDim.x - 1) {
            double rr = d_acc[0], ii = d_acc[1];
            out[0] = (float)(rr * rr + ii * ii);
        }
    }
}

extern "C" void kernel_launch(void* const* d_in, const int* in_sizes, int n_in,
                              void* d_out, int out_size) {
    const float* x1 = (const float*)d_in[0];
    const float* x2 = (const float*)d_in[1];
    const float* iscale = (const float*)d_in[2];
    const float* var = (const float*)d_in[3];

    qk_A<<<512, 256>>>(0, -1, -1, 1, x1, x2, iscale, var);   // G0lo, init+prep
    qk_B<<<256, 512>>>(0, 1);                                // G0hi, CZ0, G1hi
    qk_A<<<512, 256>>>(1, 2, 1, 0, x1, x2, iscale, var);     // G1lo, CZ1, G2lo
    qk_B<<<256, 512>>>(2, 3);                                // G2hi, CZ2, G3hi
    qk_A<<<512, 256>>>(3, 4, 3, 0, x1, x2, iscale, var);     // G3lo, CZ3, G4lo
    qk_B<<<256, 512>>>(4, 5);                                // G4hi, CZ4, G5hi
    qk_A<<<512, 256>>>(5, -1, 5, 0, x1, x2, iscale, var);    // G5lo, CZ5
    qk_reduce<<<148, 256>>>((float*)d_out);
}

// round 16
// speedup vs baseline: 1.4027x; 1.0439x over previous
#include <cuda_runtime.h>
#include <cuda_bf16.h>

// ---------------------------------------------------------------------------
// 18-qubit statevector fidelity |<psi2|psi1>|^2, hardware-efficient ansatz.
// R16 = R15 (staircase fusion, coalesced 11-bit B window, inline prep,
// fused reduce) + the two INDEPENDENT state chains run on two streams
// (event fork/join -> parallel graph branches). Per-state kernels use half
// grids; launch gaps/ramps/tails of one chain are hidden by the other.
// Chain (per state s): A:G0lo(init+prep) | B:G0hi,CZ0,G1hi | A:G1lo,CZ1,G2lo |
//   B:G2hi,CZ2,G3hi | A:G3lo,CZ3,G4lo | B:G4hi,CZ4,G5hi | A:G5lo,CZ5
// Join -> reduce(+|ov|^2).
// ---------------------------------------------------------------------------

#define NQ 18
#define NL 6
#define NSTATE (1 << NQ)

__device__ float2 d_psi[2][NSTATE];
__device__ float4 d_mats[2][NL][NQ][2];
__device__ double d_acc[2];
__device__ unsigned d_count;

__device__ __forceinline__ float2 cmulh(float2 a, float2 b) {
    return make_float2(a.x * b.x - a.y * b.y, a.x * b.y + a.y * b.x);
}
__device__ __forceinline__ float2 caddh(float2 a, float2 b) {
    return make_float2(a.x + b.x, a.y + b.y);
}
__device__ __forceinline__ float2 rscaleh(float r, float2 v) {
    return make_float2(r * v.x, r * v.y);
}

__device__ __forceinline__ void compute_mat(int s, int l, int q,
                                            const float* __restrict__ x1,
                                            const float* __restrict__ x2,
                                            const float* __restrict__ iscale,
                                            const float* __restrict__ var,
                                            float4& o0, float4& o1) {
    const float* x = s ? x2 : x1;
    float a = iscale[l * NQ + q] * x[q];
    float b = var[l * 2 * NQ + q];
    float c = var[l * 2 * NQ + NQ + q];

    float sa, ca, sb, cb, sc, cc;
    sincosf(0.5f * a, &sa, &ca);
    sincosf(0.5f * b, &sb, &cb);
    sincosf(0.5f * c, &sc, &cc);

    float2 X00 = make_float2(ca, 0.f), X01 = make_float2(0.f, -sa);
    float2 X10 = make_float2(0.f, -sa), X11 = make_float2(ca, 0.f);
    float2 M100 = caddh(rscaleh(cb, X00), rscaleh(-sb, X10));
    float2 M101 = caddh(rscaleh(cb, X01), rscaleh(-sb, X11));
    float2 M110 = caddh(rscaleh(sb, X00), rscaleh(cb, X10));
    float2 M111 = caddh(rscaleh(sb, X01), rscaleh(cb, X11));
    float2 e0 = make_float2(cc, -sc);
    float2 e1 = make_float2(cc, sc);
    float2 m00 = cmulh(e0, M100);
    float2 m01 = cmulh(e0, M101);
    float2 m10 = cmulh(e1, M110);
    float2 m11 = cmulh(e1, M111);
    o0 = make_float4(m00.x, m00.y, m01.x, m01.y);
    o1 = make_float4(m10.x, m10.y, m11.x, m11.y);
}

__device__ __forceinline__ void gate_pair(float2& a, float2& b, float4 c0, float4 c1) {
    float nax = fmaf(c0.z, b.x, fmaf(-c0.w, b.y, fmaf(c0.x, a.x, -c0.y * a.y)));
    float nay = fmaf(c0.z, b.y, fmaf(c0.w, b.x, fmaf(c0.x, a.y, c0.y * a.x)));
    float nbx = fmaf(c1.z, b.x, fmaf(-c1.w, b.y, fmaf(c1.x, a.x, -c1.y * a.y)));
    float nby = fmaf(c1.z, b.y, fmaf(c1.w, b.x, fmaf(c1.x, a.y, c1.y * a.x)));
    a = make_float2(nax, nay);
    b = make_float2(nbx, nby);
}

__device__ __forceinline__ float2 gate_shfl(float2 v, int mask,
                                            float cax, float cay, float cbx, float cby) {
    float px = __shfl_xor_sync(0xFFFFFFFFu, v.x, mask);
    float py = __shfl_xor_sync(0xFFFFFFFFu, v.y, mask);
    float rx = fmaf(cbx, px, fmaf(-cby, py, fmaf(cax, v.x, -cay * v.y)));
    float ry = fmaf(cbx, py, fmaf(cby, px, fmaf(cax, v.y, cay * v.x)));
    return make_float2(rx, ry);
}

__device__ __forceinline__ unsigned swzA(unsigned l) {
    return l ^ ((l >> 4) & 3u);
}
__device__ __forceinline__ unsigned swzB(unsigned l) {
    return l ^ ((l >> 4) & 3u) ^ ((l >> 6) & 8u);
}

#define SHFL_GATE_M(M, j, mask)                                               \
    {                                                                         \
        float4 c0 = (M)[2 * (j)], c1 = (M)[2 * (j) + 1];                      \
        bool hi = (lane & (mask)) != 0;                                       \
        float cax = hi ? c1.z : c0.x;                                         \
        float cay = hi ? c1.w : c0.y;                                         \
        float cbx = hi ? c1.x : c0.z;                                         \
        float cby = hi ? c1.y : c0.w;                                         \
        _Pragma("unroll") for (int k = 0; k < 4; k++)                         \
            v[k] = gate_shfl(v[k], (mask), cax, cay, cbx, cby);               \
    }

// ---------------------------------------------------------------------------
// Window-A kernel (per state): 256 blocks x 256 threads.
// m1: l = k | lane<<2 | w<<7 ; m2: l = (lane&15) | ((lane>>4)<<9) | w<<4 | k<<7
// ---------------------------------------------------------------------------
__global__ void __launch_bounds__(256) qk_A(int l1, int l2, int czf, int init, int s,
                                            const float* __restrict__ x1,
                                            const float* __restrict__ x2,
                                            const float* __restrict__ iscale,
                                            const float* __restrict__ var) {
    __shared__ float2 sm[1024];
    __shared__ float4 sM[40];
    int tid = threadIdx.x;
    int lane = tid & 31;
    unsigned w = (unsigned)(tid >> 5);
    int blk = blockIdx.x;                           // 0..255
    unsigned blkbase = ((unsigned)blk) << 10;
    float2* psi = d_psi[s];

    if (init) {
        if (tid < 10) {
            float4 o0, o1;
            compute_mat(s, 0, tid, x1, x2, iscale, var, o0, o1);
            sM[2 * tid] = o0;
            sM[2 * tid + 1] = o1;
        }
        if (blk == 0 && tid >= 32 && tid < 32 + NL * NQ) {
            int r = tid - 32;
            int l = r / NQ, q = r % NQ;
            float4 o0, o1;
            compute_mat(s, l, q, x1, x2, iscale, var, o0, o1);
            d_mats[s][l][q][0] = o0;
            d_mats[s][l][q][1] = o1;
        }
        if (s == 0 && blk == 0 && tid == 255) {
            d_acc[0] = 0.0;
            d_acc[1] = 0.0;
            d_count = 0u;
        }
    } else {
        if (tid < 20) sM[tid] = (&d_mats[s][l1][0][0])[tid];
        if (l2 >= 0 && tid >= 32 && tid < 52) sM[20 + tid - 32] = (&d_mats[s][l2][0][0])[tid - 32];
    }

    unsigned l1i = ((unsigned)lane << 2) | (w << 7);
    unsigned base2 = ((unsigned)lane & 15u) | (((unsigned)lane >> 4) << 9) | (w << 4);
    float2 v[4];

    if (init) {
#pragma unroll
        for (int k = 0; k < 4; k++) v[k] = make_float2(0.f, 0.f);
        if ((blkbase | l1i) == 0) v[0] = make_float2(1.f, 0.f);
    } else {
        const float4* p4 = (const float4*)(psi + blkbase + l1i);
        float4 a = p4[0], b = p4[1];
        v[0] = make_float2(a.x, a.y);
        v[1] = make_float2(a.z, a.w);
        v[2] = make_float2(b.x, b.y);
        v[3] = make_float2(b.z, b.w);
    }
    __syncthreads();                                // sM ready

    // round 1, m1: q0 (k s1), q1 (k s2), q2-6 (lane shfl)
    {
        float4 c0 = sM[0], c1 = sM[1];
        gate_pair(v[0], v[1], c0, c1);
        gate_pair(v[2], v[3], c0, c1);
    }
    {
        float4 c0 = sM[2], c1 = sM[3];
        gate_pair(v[0], v[2], c0, c1);
        gate_pair(v[1], v[3], c0, c1);
    }
    SHFL_GATE_M(sM, 2, 1)
    SHFL_GATE_M(sM, 3, 2)
    SHFL_GATE_M(sM, 4, 4)
    SHFL_GATE_M(sM, 5, 8)
    SHFL_GATE_M(sM, 6, 16)

    // T1: m1 -> m2
    unsigned sb1 = swzA(l1i);
#pragma unroll
    for (int k = 0; k < 4; k++) sm[sb1 ^ (unsigned)k] = v[k];
    __syncthreads();
    unsigned sb2 = swzA(base2);
#pragma unroll
    for (int k = 0; k < 4; k++) v[k] = sm[sb2 + ((unsigned)k << 7)];

    // round 1, m2: q7, q8, q9
    {
        float4 c0 = sM[14], c1 = sM[15];
        gate_pair(v[0], v[1], c0, c1);
        gate_pair(v[2], v[3], c0, c1);
    }
    {
        float4 c0 = sM[16], c1 = sM[17];
        gate_pair(v[0], v[2], c0, c1);
        gate_pair(v[1], v[3], c0, c1);
    }
    SHFL_GATE_M(sM, 9, 16)

    if (czf >= 0) {
#pragma unroll
        for (int k = 0; k < 4; k++) {
            unsigned g = blkbase + base2 + ((unsigned)k << 7);
            unsigned tm = g & (g >> 1) & 0x1FFFFu;
            if (__popc(tm) & 1) {
                v[k].x = -v[k].x;
                v[k].y = -v[k].y;
            }
        }
    }

    if (l2 < 0) {
#pragma unroll
        for (int k = 0; k < 4; k++)
            psi[blkbase + base2 + ((unsigned)k << 7)] = v[k];
        return;
    }

    const float4* M2 = sM + 20;
    // round 2, m2 gates first (same-layer gates commute): q7, q8, q9
    {
        float4 c0 = M2[14], c1 = M2[15];
        gate_pair(v[0], v[1], c0, c1);
        gate_pair(v[2], v[3], c0, c1);
    }
    {
        float4 c0 = M2[16], c1 = M2[17];
        gate_pair(v[0], v[2], c0, c1);
        gate_pair(v[1], v[3], c0, c1);
    }
    SHFL_GATE_M(M2, 9, 16)

    // T-back: m2 -> m1
    __syncthreads();
#pragma unroll
    for (int k = 0; k < 4; k++) sm[sb2 + ((unsigned)k << 7)] = v[k];
    __syncthreads();
#pragma unroll
    for (int k = 0; k < 4; k++) v[k] = sm[sb1 ^ (unsigned)k];

    // round 2, m1: q0, q1, q2-6
    {
        float4 c0 = M2[0], c1 = M2[1];
        gate_pair(v[0], v[1], c0, c1);
        gate_pair(v[2], v[3], c0, c1);
    }
    {
        float4 c0 = M2[2], c1 = M2[3];
        gate_pair(v[0], v[2], c0, c1);
        gate_pair(v[1], v[3], c0, c1);
    }
    SHFL_GATE_M(M2, 2, 1)
    SHFL_GATE_M(M2, 3, 2)
    SHFL_GATE_M(M2, 4, 4)
    SHFL_GATE_M(M2, 5, 8)
    SHFL_GATE_M(M2, 6, 16)

    {
        float4* p4 = (float4*)(psi + blkbase + l1i);
        p4[0] = make_float4(v[0].x, v[0].y, v[1].x, v[1].y);
        p4[1] = make_float4(v[2].x, v[2].y, v[3].x, v[3].y);
    }
}

// ---------------------------------------------------------------------------
// Window-B kernel (per state, always fused): 128 blocks x 512 threads.
// Window {0,1,2, 10..17}: g(l) = (l&7) | rest<<3 | (l>>3)<<10.
// ---------------------------------------------------------------------------
__global__ void __launch_bounds__(512) qk_B(int l1, int l2, int s) {
    __shared__ float2 sm[2048];
    __shared__ float4 sM[32];
    int tid = threadIdx.x;
    int lane = tid & 31;
    unsigned w = (unsigned)(tid >> 5);              // 0..15
    unsigned rest = (unsigned)blockIdx.x;           // 0..127 -> g bits 3-9
    float2* psi = d_psi[s];

    if (tid < 16) sM[tid] = (&d_mats[s][l1][10][0])[tid];
    if (tid >= 32 && tid < 48) sM[16 + tid - 32] = (&d_mats[s][l2][10][0])[tid - 32];

    unsigned l1i = ((unsigned)lane << 2) | (w << 7);
    unsigned g1 = (l1i & 7u) | (rest << 3) | ((l1i >> 3) << 10);

    float2 v[4];
    {
        const float4* p4 = (const float4*)(psi + g1);
        float4 a = p4[0], b = p4[1];
        v[0] = make_float2(a.x, a.y);
        v[1] = make_float2(a.z, a.w);
        v[2] = make_float2(b.x, b.y);
        v[3] = make_float2(b.z, b.w);
    }
    __syncthreads();                                // sM ready

    // round 1, m1: q10..q13 (lane shfl masks 2,4,8,16)
    SHFL_GATE_M(sM, 0, 2)
    SHFL_GATE_M(sM, 1, 4)
    SHFL_GATE_M(sM, 2, 8)
    SHFL_GATE_M(sM, 3, 16)

    // T1: m1 -> m2
    unsigned sb1 = swzB(l1i);
#pragma unroll
    for (int k = 0; k < 4; k++) sm[sb1 ^ (unsigned)k] = v[k];
    __syncthreads();
    unsigned l2i = ((unsigned)lane & 7u) | (w << 3) | (((unsigned)lane >> 3) << 9);
    unsigned sb2 = swzB(l2i);
#pragma unroll
    for (int k = 0; k < 4; k++) v[k] = sm[sb2 + ((unsigned)k << 7)];

    // round 1, m2: q14 (k' s1), q15 (k' s2), q16 (mask 8), q17 (mask 16)
    {
        float4 c0 = sM[8], c1 = sM[9];
        gate_pair(v[0], v[1], c0, c1);
        gate_pair(v[2], v[3], c0, c1);
    }
    {
        float4 c0 = sM[10], c1 = sM[11];
        gate_pair(v[0], v[2], c0, c1);
        gate_pair(v[1], v[3], c0, c1);
    }
    SHFL_GATE_M(sM, 6, 8)
    SHFL_GATE_M(sM, 7, 16)

    // CZ chain sign (layer l1 complete)
#pragma unroll
    for (int k = 0; k < 4; k++) {
        unsigned lk = l2i | ((unsigned)k << 7);
        unsigned g = (lk & 7u) | (rest << 3) | ((lk >> 3) << 10);
        unsigned tm = g & (g >> 1) & 0x1FFFFu;
        if (__popc(tm) & 1) {
            v[k].x = -v[k].x;
            v[k].y = -v[k].y;
        }
    }

    const float4* M2 = sM + 16;
    // round 2, m2 gates first: q14, q15, q16, q17
    {
        float4 c0 = M2[8], c1 = M2[9];
        gate_pair(v[0], v[1], c0, c1);
        gate_pair(v[2], v[3], c0, c1);
    }
    {
        float4 c0 = M2[10], c1 = M2[11];
        gate_pair(v[0], v[2], c0, c1);
        gate_pair(v[1], v[3], c0, c1);
    }
    SHFL_GATE_M(M2, 6, 8)
    SHFL_GATE_M(M2, 7, 16)

    // T-back: m2 -> m1
    __syncthreads();
#pragma unroll
    for (int k = 0; k < 4; k++) sm[sb2 + ((unsigned)k << 7)] = v[k];
    __syncthreads();
#pragma unroll
    for (int k = 0; k < 4; k++) v[k] = sm[sb1 ^ (unsigned)k];

    // round 2, m1: q10..q13
    SHFL_GATE_M(M2, 0, 2)
    SHFL_GATE_M(M2, 1, 4)
    SHFL_GATE_M(M2, 2, 8)
    SHFL_GATE_M(M2, 3, 16)

    {
        float4* p4 = (float4*)(psi + g1);
        p4[0] = make_float4(v[0].x, v[0].y, v[1].x, v[1].y);
        p4[1] = make_float4(v[2].x, v[2].y, v[3].x, v[3].y);
    }
}

// ---------------------------------------------------------------------------
// Overlap reduction + finalization (last arriving block computes |ov|^2)
// ---------------------------------------------------------------------------
__global__ void qk_reduce(float* out) {
    int t = blockIdx.x * blockDim.x + threadIdx.x;
    int nthreads = gridDim.x * blockDim.x;
    double re = 0.0, im = 0.0;
    for (int i = t; i < NSTATE; i += nthreads) {
        float2 a = d_psi[0][i];
        float2 b = d_psi[1][i];
        re += (double)b.x * a.x + (double)b.y * a.y;
        im += (double)b.x * a.y - (double)b.y * a.x;
    }
#pragma unroll
    for (int o = 16; o > 0; o >>= 1) {
        re += __shfl_down_sync(0xFFFFFFFFu, re, o);
        im += __shfl_down_sync(0xFFFFFFFFu, im, o);
    }
    if ((threadIdx.x & 31) == 0) {
        atomicAdd(&d_acc[0], re);
        atomicAdd(&d_acc[1], im);
    }
    __syncthreads();
    if (threadIdx.x == 0) {
        __threadfence();
        unsigned done = atomicAdd(&d_count, 1u);
        if (done == gridDim.x - 1) {
            double rr = d_acc[0], ii = d_acc[1];
            out[0] = (float)(rr * rr + ii * ii);
        }
    }
}

// One-time host-side handles (host resources only; no device memory).
static cudaStream_t g_s2 = 0;
static cudaEvent_t g_fork = 0, g_join = 0;

extern "C" void kernel_launch(void* const* d_in, const int* in_sizes, int n_in,
                              void* d_out, int out_size) {
    const float* x1 = (const float*)d_in[0];
    const float* x2 = (const float*)d_in[1];
    const float* iscale = (const float*)d_in[2];
    const float* var = (const float*)d_in[3];
    float* out = (float*)d_out;

    if (g_s2 == 0) {
        cudaStreamCreateWithFlags(&g_s2, cudaStreamNonBlocking);
        cudaEventCreateWithFlags(&g_fork, cudaEventDisableTiming);
        cudaEventCreateWithFlags(&g_join, cudaEventDisableTiming);
    }

    // fork: bring g_s2 into the same dependency chain (and capture graph)
    cudaEventRecord(g_fork, 0);
    cudaStreamWaitEvent(g_s2, g_fork, 0);

    // chain for state 0 on the default stream
    qk_A<<<256, 256, 0, 0>>>(0, -1, -1, 1, 0, x1, x2, iscale, var);
    qk_B<<<128, 512, 0, 0>>>(0, 1, 0);
    qk_A<<<256, 256, 0, 0>>>(1, 2, 1, 0, 0, x1, x2, iscale, var);
    qk_B<<<128, 512, 0, 0>>>(2, 3, 0);
    qk_A<<<256, 256, 0, 0>>>(3, 4, 3, 0, 0, x1, x2, iscale, var);
    qk_B<<<128, 512, 0, 0>>>(4, 5, 0);
    qk_A<<<256, 256, 0, 0>>>(5, -1, 5, 0, 0, x1, x2, iscale, var);

    // chain for state 1 on g_s2
    qk_A<<<256, 256, 0, g_s2>>>(0, -1, -1, 1, 1, x1, x2, iscale, var);
    qk_B<<<128, 512, 0, g_s2>>>(0, 1, 1);
    qk_A<<<256, 256, 0, g_s2>>>(1, 2, 1, 0, 1, x1, x2, iscale, var);
    qk_B<<<128, 512, 0, g_s2>>>(2, 3, 1);
    qk_A<<<256, 256, 0, g_s2>>>(3, 4, 3, 0, 1, x1, x2, iscale, var);
    qk_B<<<128, 512, 0, g_s2>>>(4, 5, 1);
    qk_A<<<256, 256, 0, g_s2>>>(5, -1, 5, 0, 1, x1, x2, iscale, var);

    // join: reduce depends on both chains
    cudaEventRecord(g_join, g_s2);
    cudaStreamWaitEvent(0, g_join, 0);
    qk_reduce<<<148, 256, 0, 0>>>(out);
}

// round 17
// speedup vs baseline: 1.4951x; 1.0659x over previous
#include <cuda_runtime.h>
#include <cuda_bf16.h>

// ---------------------------------------------------------------------------
// 18-qubit statevector fidelity |<psi2|psi1>|^2, hardware-efficient ansatz.
// R17 = R16 (staircase, 11-bit B window, two overlapped per-state chains,
// fused reduce) + PRODUCT-STATE INITIALIZATION: after layer 0 on |0..0> the
// state is a product state amp(g) = prod_q col0(M0_q)[g_q], so sweep 1 and
// the G0hi round collapse into a closed form (~17 cmuls/thread). The first
// kernel qk_B0 computes product amps, applies CZ0, runs layer-1's hi round.
// Chain per state: B0:prod(G0)+CZ0+G1hi | A:G1lo,CZ1,G2lo | B:G2hi,CZ2,G3hi |
//   A:G3lo,CZ3,G4lo | B:G4hi,CZ4,G5hi | A:G5lo,CZ5  -> join -> reduce.
// 6 sweeps/chain (was 7), 13 graph nodes.
// ---------------------------------------------------------------------------

#define NQ 18
#define NL 6
#define NSTATE (1 << NQ)

__device__ float2 d_psi[2][NSTATE];
__device__ float4 d_mats[2][NL][NQ][2];
__device__ double d_acc[2];
__device__ unsigned d_count;

__device__ __forceinline__ float2 cmulh(float2 a, float2 b) {
    return make_float2(a.x * b.x - a.y * b.y, a.x * b.y + a.y * b.x);
}
__device__ __forceinline__ float2 caddh(float2 a, float2 b) {
    return make_float2(a.x + b.x, a.y + b.y);
}
__device__ __forceinline__ float2 rscaleh(float r, float2 v) {
    return make_float2(r * v.x, r * v.y);
}

__device__ __forceinline__ void compute_mat(int s, int l, int q,
                                            const float* __restrict__ x1,
                                            const float* __restrict__ x2,
                                            const float* __restrict__ iscale,
                                            const float* __restrict__ var,
                                            float4& o0, float4& o1) {
    const float* x = s ? x2 : x1;
    float a = iscale[l * NQ + q] * x[q];
    float b = var[l * 2 * NQ + q];
    float c = var[l * 2 * NQ + NQ + q];

    float sa, ca, sb, cb, sc, cc;
    sincosf(0.5f * a, &sa, &ca);
    sincosf(0.5f * b, &sb, &cb);
    sincosf(0.5f * c, &sc, &cc);

    float2 X00 = make_float2(ca, 0.f), X01 = make_float2(0.f, -sa);
    float2 X10 = make_float2(0.f, -sa), X11 = make_float2(ca, 0.f);
    float2 M100 = caddh(rscaleh(cb, X00), rscaleh(-sb, X10));
    float2 M101 = caddh(rscaleh(cb, X01), rscaleh(-sb, X11));
    float2 M110 = caddh(rscaleh(sb, X00), rscaleh(cb, X10));
    float2 M111 = caddh(rscaleh(sb, X01), rscaleh(cb, X11));
    float2 e0 = make_float2(cc, -sc);
    float2 e1 = make_float2(cc, sc);
    float2 m00 = cmulh(e0, M100);
    float2 m01 = cmulh(e0, M101);
    float2 m10 = cmulh(e1, M110);
    float2 m11 = cmulh(e1, M111);
    o0 = make_float4(m00.x, m00.y, m01.x, m01.y);
    o1 = make_float4(m10.x, m10.y, m11.x, m11.y);
}

__device__ __forceinline__ void gate_pair(float2& a, float2& b, float4 c0, float4 c1) {
    float nax = fmaf(c0.z, b.x, fmaf(-c0.w, b.y, fmaf(c0.x, a.x, -c0.y * a.y)));
    float nay = fmaf(c0.z, b.y, fmaf(c0.w, b.x, fmaf(c0.x, a.y, c0.y * a.x)));
    float nbx = fmaf(c1.z, b.x, fmaf(-c1.w, b.y, fmaf(c1.x, a.x, -c1.y * a.y)));
    float nby = fmaf(c1.z, b.y, fmaf(c1.w, b.x, fmaf(c1.x, a.y, c1.y * a.x)));
    a = make_float2(nax, nay);
    b = make_float2(nbx, nby);
}

__device__ __forceinline__ float2 gate_shfl(float2 v, int mask,
                                            float cax, float cay, float cbx, float cby) {
    float px = __shfl_xor_sync(0xFFFFFFFFu, v.x, mask);
    float py = __shfl_xor_sync(0xFFFFFFFFu, v.y, mask);
    float rx = fmaf(cbx, px, fmaf(-cby, py, fmaf(cax, v.x, -cay * v.y)));
    float ry = fmaf(cbx, py, fmaf(cby, px, fmaf(cax, v.y, cay * v.x)));
    return make_float2(rx, ry);
}

__device__ __forceinline__ unsigned swzA(unsigned l) {
    return l ^ ((l >> 4) & 3u);
}
__device__ __forceinline__ unsigned swzB(unsigned l) {
    return l ^ ((l >> 4) & 3u) ^ ((l >> 6) & 8u);
}

#define SHFL_GATE_M(M, j, mask)                                               \
    {                                                                         \
        float4 c0 = (M)[2 * (j)], c1 = (M)[2 * (j) + 1];                      \
        bool hi = (lane & (mask)) != 0;                                       \
        float cax = hi ? c1.z : c0.x;                                         \
        float cay = hi ? c1.w : c0.y;                                         \
        float cbx = hi ? c1.x : c0.z;                                         \
        float cby = hi ? c1.y : c0.w;                                         \
        _Pragma("unroll") for (int k = 0; k < 4; k++)                         \
            v[k] = gate_shfl(v[k], (mask), cax, cay, cbx, cby);               \
    }

// ---------------------------------------------------------------------------
// qk_B0 (per state): product-state init (layer 0 on |0>), CZ0, layer-1 hi
// round. Window B = {0,1,2, 10..17}: g(l) = (l&7) | rest<<3 | (l>>3)<<10.
// 128 blocks x 512 threads. Block 0 also writes all d_mats[s].
// ---------------------------------------------------------------------------
__global__ void __launch_bounds__(512) qk_B0(int s,
                                             const float* __restrict__ x1,
                                             const float* __restrict__ x2,
                                             const float* __restrict__ iscale,
                                             const float* __restrict__ var) {
    __shared__ float2 sm[2048];
    __shared__ float4 sM[16];       // layer 1, q10..17
    __shared__ float2 sF[NQ][2];    // layer 0 column 0 per qubit: [q][bit]
    int tid = threadIdx.x;
    int lane = tid & 31;
    unsigned w = (unsigned)(tid >> 5);              // 0..15
    unsigned rest = (unsigned)blockIdx.x;           // 0..127 -> g bits 3-9
    float2* psi = d_psi[s];

    if (tid < NQ) {
        float4 o0, o1;
        compute_mat(s, 0, tid, x1, x2, iscale, var, o0, o1);
        sF[tid][0] = make_float2(o0.x, o0.y);       // m00
        sF[tid][1] = make_float2(o1.x, o1.y);       // m10
    }
    if (tid >= 32 && tid < 40) {
        int j = tid - 32;
        float4 o0, o1;
        compute_mat(s, 1, 10 + j, x1, x2, iscale, var, o0, o1);
        sM[2 * j] = o0;
        sM[2 * j + 1] = o1;
    }
    if (blockIdx.x == 0 && tid >= 64 && tid < 64 + NL * NQ) {
        int r = tid - 64;
        int l = r / NQ, q = r % NQ;
        float4 o0, o1;
        compute_mat(s, l, q, x1, x2, iscale, var, o0, o1);
        d_mats[s][l][q][0] = o0;
        d_mats[s][l][q][1] = o1;
    }
    if (s == 0 && blockIdx.x == 0 && tid == 511) {
        d_acc[0] = 0.0;
        d_acc[1] = 0.0;
        d_count = 0u;
    }
    __syncthreads();

    // m1 layout: l = k | lane<<2 | w<<7 ;  local bits: b0,b1=k, b2=lane.0,
    // b3-6=lane.1-4 (g10-13), b7-10=w (g14-17); g3-9 = rest.
    unsigned l1i = ((unsigned)lane << 2) | (w << 7);
    unsigned g1 = (l1i & 7u) | (rest << 3) | ((l1i >> 3) << 10);

    // product of fixed-bit factors (bits 2..17 of g)
    float2 base = sF[2][lane & 1];
#pragma unroll
    for (int q = 3; q < 10; q++) base = cmulh(base, sF[q][(rest >> (q - 3)) & 1]);
#pragma unroll
    for (int j = 0; j < 4; j++) base = cmulh(base, sF[10 + j][(lane >> (1 + j)) & 1]);
#pragma unroll
    for (int j = 0; j < 4; j++) base = cmulh(base, sF[14 + j][(w >> j) & 1]);

    float2 v[4];
#pragma unroll
    for (int k = 0; k < 4; k++) {
        float2 t = cmulh(base, sF[0][k & 1]);
        v[k] = cmulh(t, sF[1][(k >> 1) & 1]);
        // CZ0 sign
        unsigned g = g1 | (unsigned)k;
        unsigned tm = g & (g >> 1) & 0x1FFFFu;
        if (__popc(tm) & 1) {
            v[k].x = -v[k].x;
            v[k].y = -v[k].y;
        }
    }

    // layer-1 hi round: m1 gates q10..q13 (lane shfl masks 2,4,8,16)
    SHFL_GATE_M(sM, 0, 2)
    SHFL_GATE_M(sM, 1, 4)
    SHFL_GATE_M(sM, 2, 8)
    SHFL_GATE_M(sM, 3, 16)

    // T1: m1 -> m2
    unsigned sb1 = swzB(l1i);
#pragma unroll
    for (int k = 0; k < 4; k++) sm[sb1 ^ (unsigned)k] = v[k];
    __syncthreads();
    unsigned l2i = ((unsigned)lane & 7u) | (w << 3) | (((unsigned)lane >> 3) << 9);
    unsigned sb2 = swzB(l2i);
#pragma unroll
    for (int k = 0; k < 4; k++) v[k] = sm[sb2 + ((unsigned)k << 7)];

    // m2 gates: q14 (k' s1), q15 (k' s2), q16 (mask 8), q17 (mask 16)
    {
        float4 c0 = sM[8], c1 = sM[9];
        gate_pair(v[0], v[1], c0, c1);
        gate_pair(v[2], v[3], c0, c1);
    }
    {
        float4 c0 = sM[10], c1 = sM[11];
        gate_pair(v[0], v[2], c0, c1);
        gate_pair(v[1], v[3], c0, c1);
    }
    SHFL_GATE_M(sM, 6, 8)
    SHFL_GATE_M(sM, 7, 16)

    // store (m2 layout -> natural indices)
#pragma unroll
    for (int k = 0; k < 4; k++) {
        unsigned lk = l2i | ((unsigned)k << 7);
        unsigned g = (lk & 7u) | (rest << 3) | ((lk >> 3) << 10);
        psi[g] = v[k];
    }
}

// ---------------------------------------------------------------------------
// Window-A kernel (per state, always fused): 256 blocks x 256 threads.
// Gates q0-9 of l1 and (l2 if >=0); CZ(czf) after l1 round.
// m1: l = k | lane<<2 | w<<7 ; m2: l = (lane&15) | ((lane>>4)<<9) | w<<4 | k<<7
// ---------------------------------------------------------------------------
__global__ void __launch_bounds__(256) qk_A(int l1, int l2, int czf, int s) {
    __shared__ float2 sm[1024];
    __shared__ float4 sM[40];
    int tid = threadIdx.x;
    int lane = tid & 31;
    unsigned w = (unsigned)(tid >> 5);
    unsigned blkbase = ((unsigned)blockIdx.x) << 10;
    float2* psi = d_psi[s];

    if (tid < 20) sM[tid] = (&d_mats[s][l1][0][0])[tid];
    if (l2 >= 0 && tid >= 32 && tid < 52) sM[20 + tid - 32] = (&d_mats[s][l2][0][0])[tid - 32];

    unsigned l1i = ((unsigned)lane << 2) | (w << 7);
    unsigned base2 = ((unsigned)lane & 15u) | (((unsigned)lane >> 4) << 9) | (w << 4);
    float2 v[4];
    {
        const float4* p4 = (const float4*)(psi + blkbase + l1i);
        float4 a = p4[0], b = p4[1];
        v[0] = make_float2(a.x, a.y);
        v[1] = make_float2(a.z, a.w);
        v[2] = make_float2(b.x, b.y);
        v[3] = make_float2(b.z, b.w);
    }
    __syncthreads();                                // sM ready

    // round 1, m1: q0 (k s1), q1 (k s2), q2-6 (lane shfl)
    {
        float4 c0 = sM[0], c1 = sM[1];
        gate_pair(v[0], v[1], c0, c1);
        gate_pair(v[2], v[3], c0, c1);
    }
    {
        float4 c0 = sM[2], c1 = sM[3];
        gate_pair(v[0], v[2], c0, c1);
        gate_pair(v[1], v[3], c0, c1);
    }
    SHFL_GATE_M(sM, 2, 1)
    SHFL_GATE_M(sM, 3, 2)
    SHFL_GATE_M(sM, 4, 4)
    SHFL_GATE_M(sM, 5, 8)
    SHFL_GATE_M(sM, 6, 16)

    // T1: m1 -> m2
    unsigned sb1 = swzA(l1i);
#pragma unroll
    for (int k = 0; k < 4; k++) sm[sb1 ^ (unsigned)k] = v[k];
    __syncthreads();
    unsigned sb2 = swzA(base2);
#pragma unroll
    for (int k = 0; k < 4; k++) v[k] = sm[sb2 + ((unsigned)k << 7)];

    // round 1, m2: q7, q8, q9
    {
        float4 c0 = sM[14], c1 = sM[15];
        gate_pair(v[0], v[1], c0, c1);
        gate_pair(v[2], v[3], c0, c1);
    }
    {
        float4 c0 = sM[16], c1 = sM[17];
        gate_pair(v[0], v[2], c0, c1);
        gate_pair(v[1], v[3], c0, c1);
    }
    SHFL_GATE_M(sM, 9, 16)

    if (czf >= 0) {
#pragma unroll
        for (int k = 0; k < 4; k++) {
            unsigned g = blkbase + base2 + ((unsigned)k << 7);
            unsigned tm = g & (g >> 1) & 0x1FFFFu;
            if (__popc(tm) & 1) {
                v[k].x = -v[k].x;
                v[k].y = -v[k].y;
            }
        }
    }

    if (l2 < 0) {
#pragma unroll
        for (int k = 0; k < 4; k++)
            psi[blkbase + base2 + ((unsigned)k << 7)] = v[k];
        return;
    }

    const float4* M2 = sM + 20;
    // round 2, m2 gates first (same-layer gates commute): q7, q8, q9
    {
        float4 c0 = M2[14], c1 = M2[15];
        gate_pair(v[0], v[1], c0, c1);
        gate_pair(v[2], v[3], c0, c1);
    }
    {
        float4 c0 = M2[16], c1 = M2[17];
        gate_pair(v[0], v[2], c0, c1);
        gate_pair(v[1], v[3], c0, c1);
    }
    SHFL_GATE_M(M2, 9, 16)

    // T-back: m2 -> m1
    __syncthreads();
#pragma unroll
    for (int k = 0; k < 4; k++) sm[sb2 + ((unsigned)k << 7)] = v[k];
    __syncthreads();
#pragma unroll
    for (int k = 0; k < 4; k++) v[k] = sm[sb1 ^ (unsigned)k];

    // round 2, m1: q0, q1, q2-6
    {
        float4 c0 = M2[0], c1 = M2[1];
        gate_pair(v[0], v[1], c0, c1);
        gate_pair(v[2], v[3], c0, c1);
    }
    {
        float4 c0 = M2[2], c1 = M2[3];
        gate_pair(v[0], v[2], c0, c1);
        gate_pair(v[1], v[3], c0, c1);
    }
    SHFL_GATE_M(M2, 2, 1)
    SHFL_GATE_M(M2, 3, 2)
    SHFL_GATE_M(M2, 4, 4)
    SHFL_GATE_M(M2, 5, 8)
    SHFL_GATE_M(M2, 6, 16)

    {
        float4* p4 = (float4*)(psi + blkbase + l1i);
        p4[0] = make_float4(v[0].x, v[0].y, v[1].x, v[1].y);
        p4[1] = make_float4(v[2].x, v[2].y, v[3].x, v[3].y);
    }
}

// ---------------------------------------------------------------------------
// Window-B kernel (per state, always fused): 128 blocks x 512 threads.
// Gates q10-17 of l1 and l2, CZ after l1 round.
// ---------------------------------------------------------------------------
__global__ void __launch_bounds__(512) qk_B(int l1, int l2, int s) {
    __shared__ float2 sm[2048];
    __shared__ float4 sM[32];
    int tid = threadIdx.x;
    int lane = tid & 31;
    unsigned w = (unsigned)(tid >> 5);
    unsigned rest = (unsigned)blockIdx.x;
    float2* psi = d_psi[s];

    if (tid < 16) sM[tid] = (&d_mats[s][l1][10][0])[tid];
    if (tid >= 32 && tid < 48) sM[16 + tid - 32] = (&d_mats[s][l2][10][0])[tid - 32];

    unsigned l1i = ((unsigned)lane << 2) | (w << 7);
    unsigned g1 = (l1i & 7u) | (rest << 3) | ((l1i >> 3) << 10);

    float2 v[4];
    {
        const float4* p4 = (const float4*)(psi + g1);
        float4 a = p4[0], b = p4[1];
        v[0] = make_float2(a.x, a.y);
        v[1] = make_float2(a.z, a.w);
        v[2] = make_float2(b.x, b.y);
        v[3] = make_float2(b.z, b.w);
    }
    __syncthreads();                                // sM ready

    // round 1, m1: q10..q13
    SHFL_GATE_M(sM, 0, 2)
    SHFL_GATE_M(sM, 1, 4)
    SHFL_GATE_M(sM, 2, 8)
    SHFL_GATE_M(sM, 3, 16)

    unsigned sb1 = swzB(l1i);
#pragma unroll
    for (int k = 0; k < 4; k++) sm[sb1 ^ (unsigned)k] = v[k];
    __syncthreads();
    unsigned l2i = ((unsigned)lane & 7u) | (w << 3) | (((unsigned)lane >> 3) << 9);
    unsigned sb2 = swzB(l2i);
#pragma unroll
    for (int k = 0; k < 4; k++) v[k] = sm[sb2 + ((unsigned)k << 7)];

    // round 1, m2: q14, q15, q16, q17
    {
        float4 c0 = sM[8], c1 = sM[9];
        gate_pair(v[0], v[1], c0, c1);
        gate_pair(v[2], v[3], c0, c1);
    }
    {
        float4 c0 = sM[10], c1 = sM[11];
        gate_pair(v[0], v[2], c0, c1);
        gate_pair(v[1], v[3], c0, c1);
    }
    SHFL_GATE_M(sM, 6, 8)
    SHFL_GATE_M(sM, 7, 16)

    // CZ chain sign (layer l1 complete)
#pragma unroll
    for (int k = 0; k < 4; k++) {
        unsigned lk = l2i | ((unsigned)k << 7);
        unsigned g = (lk & 7u) | (rest << 3) | ((lk >> 3) << 10);
        unsigned tm = g & (g >> 1) & 0x1FFFFu;
        if (__popc(tm) & 1) {
            v[k].x = -v[k].x;
            v[k].y = -v[k].y;
        }
    }

    const float4* M2 = sM + 16;
    // round 2, m2 gates first
    {
        float4 c0 = M2[8], c1 = M2[9];
        gate_pair(v[0], v[1], c0, c1);
        gate_pair(v[2], v[3], c0, c1);
    }
    {
        float4 c0 = M2[10], c1 = M2[11];
        gate_pair(v[0], v[2], c0, c1);
        gate_pair(v[1], v[3], c0, c1);
    }
    SHFL_GATE_M(M2, 6, 8)
    SHFL_GATE_M(M2, 7, 16)

    // T-back
    __syncthreads();
#pragma unroll
    for (int k = 0; k < 4; k++) sm[sb2 + ((unsigned)k << 7)] = v[k];
    __syncthreads();
#pragma unroll
    for (int k = 0; k < 4; k++) v[k] = sm[sb1 ^ (unsigned)k];

    // round 2, m1: q10..q13
    SHFL_GATE_M(M2, 0, 2)
    SHFL_GATE_M(M2, 1, 4)
    SHFL_GATE_M(M2, 2, 8)
    SHFL_GATE_M(M2, 3, 16)

    {
        float4* p4 = (float4*)(psi + g1);
        p4[0] = make_float4(v[0].x, v[0].y, v[1].x, v[1].y);
        p4[1] = make_float4(v[2].x, v[2].y, v[3].x, v[3].y);
    }
}

// ---------------------------------------------------------------------------
// Overlap reduction + finalization
// ---------------------------------------------------------------------------
__global__ void qk_reduce(float* out) {
    int t = blockIdx.x * blockDim.x + threadIdx.x;
    int nthreads = gridDim.x * blockDim.x;
    double re = 0.0, im = 0.0;
    for (int i = t; i < NSTATE; i += nthreads) {
        float2 a = d_psi[0][i];
        float2 b = d_psi[1][i];
        re += (double)b.x * a.x + (double)b.y * a.y;
        im += (double)b.x * a.y - (double)b.y * a.x;
    }
#pragma unroll
    for (int o = 16; o > 0; o >>= 1) {
        re += __shfl_down_sync(0xFFFFFFFFu, re, o);
        im += __shfl_down_sync(0xFFFFFFFFu, im, o);
    }
    if ((threadIdx.x & 31) == 0) {
        atomicAdd(&d_acc[0], re);
        atomicAdd(&d_acc[1], im);
    }
    __syncthreads();
    if (threadIdx.x == 0) {
        __threadfence();
        unsigned done = atomicAdd(&d_count, 1u);
        if (done == gridDim.x - 1) {
            double rr = d_acc[0], ii = d_acc[1];
            out[0] = (float)(rr * rr + ii * ii);
        }
    }
}

// One-time host-side handles (host resources only; no device memory).
static cudaStream_t g_s2 = 0;
static cudaEvent_t g_fork = 0, g_join = 0;

extern "C" void kernel_launch(void* const* d_in, const int* in_sizes, int n_in,
                              void* d_out, int out_size) {
    const float* x1 = (const float*)d_in[0];
    const float* x2 = (const float*)d_in[1];
    const float* iscale = (const float*)d_in[2];
    const float* var = (const float*)d_in[3];
    float* out = (float*)d_out;

    if (g_s2 == 0) {
        cudaStreamCreateWithFlags(&g_s2, cudaStreamNonBlocking);
        cudaEventCreateWithFlags(&g_fork, cudaEventDisableTiming);
        cudaEventCreateWithFlags(&g_join, cudaEventDisableTiming);
    }

    cudaEventRecord(g_fork, 0);
    cudaStreamWaitEvent(g_s2, g_fork, 0);

    // chain for state 0 (default stream)
    qk_B0<<<128, 512, 0, 0>>>(0, x1, x2, iscale, var);   // prod(G0), CZ0, G1hi
    qk_A<<<256, 256, 0, 0>>>(1, 2, 1, 0);                // G1lo, CZ1, G2lo
    qk_B<<<128, 512, 0, 0>>>(2, 3, 0);                   // G2hi, CZ2, G3hi
    qk_A<<<256, 256, 0, 0>>>(3, 4, 3, 0);                // G3lo, CZ3, G4lo
    qk_B<<<128, 512, 0, 0>>>(4, 5, 0);                   // G4hi, CZ4, G5hi
    qk_A<<<256, 256, 0, 0>>>(5, -1, 5, 0);               // G5lo, CZ5

    // chain for state 1 (g_s2)
    qk_B0<<<128, 512, 0, g_s2>>>(1, x1, x2, iscale, var);
    qk_A<<<256, 256, 0, g_s2>>>(1, 2, 1, 1);
    qk_B<<<128, 512, 0, g_s2>>>(2, 3, 1);
    qk_A<<<256, 256, 0, g_s2>>>(3, 4, 3, 1);
    qk_B<<<128, 512, 0, g_s2>>>(4, 5, 1);
    qk_A<<<256, 256, 0, g_s2>>>(5, -1, 5, 1);

    cudaEventRecord(g_join, g_s2);
    cudaStreamWaitEvent(0, g_join, 0);
    qk_reduce<<<148, 256, 0, 0>>>(out);
}